// round 1
// baseline (speedup 1.0000x reference)
#include <cuda_runtime.h>
#include <cuda_bf16.h>
#include <cstddef>

// Problem constants (CasualAttention_30940944400931)
//   x:      [1, 2048, 1024] fp32
//   W_qkv:  [1024, 3072], b_qkv: [3072]
//   W_out:  [1024, 1024], b_out: [1024]
//   heads: 64 heads of dim 16 (channel n*16+d belongs to head n)
//   out:    [1, 2048, 1024] fp32

#define T_SEQ   2048
#define C_EMB   1024
#define HDIM    16
#define NHEADS  64

// Scratch (no cudaMalloc allowed)
__device__ float g_qkv[T_SEQ * 3 * C_EMB];   // 25.2 MB
__device__ float g_attn[T_SEQ * C_EMB];      // 8.4 MB

// ---------------------------------------------------------------------------
// SGEMM: C[M,N] = A[M,K] @ B[K,N] + bias[N]
// 128x128 block tile, BK=8, 256 threads, 8x8 per thread (split 4+4 for
// conflict-free float4 smem reads). M,N,K assumed multiples of tile sizes.
// ---------------------------------------------------------------------------
__global__ __launch_bounds__(256) void gemm_bias_kernel(
    const float* __restrict__ A, const float* __restrict__ B,
    const float* __restrict__ bias, float* __restrict__ C,
    int M, int N, int K)
{
    const int BM = 128, BN = 128, BK = 8;
    __shared__ float As[BK][BM];
    __shared__ float Bs[BK][BN];

    const int tid = threadIdx.x;          // 0..255
    const int tx  = tid & 15;             // 0..15
    const int ty  = tid >> 4;             // 0..15
    const int row0 = blockIdx.y * BM;
    const int col0 = blockIdx.x * BN;

    // A tile load mapping: 128 rows x 8 cols = 256 float4 (2 per row)
    const int a_row = tid >> 1;                 // 0..127
    const int a_c4  = (tid & 1) * 4;            // 0 or 4
    // B tile load mapping: 8 rows x 128 cols = 256 float4
    const int b_row = tid >> 5;                 // 0..7
    const int b_c4  = (tid & 31) * 4;           // 0..124

    float acc[8][8];
#pragma unroll
    for (int i = 0; i < 8; i++)
#pragma unroll
        for (int j = 0; j < 8; j++) acc[i][j] = 0.f;

    const float* Aptr = A + (size_t)(row0 + a_row) * K + a_c4;
    const float* Bptr = B + (size_t)b_row * N + col0 + b_c4;

    for (int k0 = 0; k0 < K; k0 += BK) {
        float4 av = *(const float4*)(Aptr + k0);
        As[a_c4 + 0][a_row] = av.x;
        As[a_c4 + 1][a_row] = av.y;
        As[a_c4 + 2][a_row] = av.z;
        As[a_c4 + 3][a_row] = av.w;
        float4 bv = *(const float4*)(Bptr + (size_t)k0 * N);
        *(float4*)&Bs[b_row][b_c4] = bv;
        __syncthreads();

#pragma unroll
        for (int k = 0; k < BK; k++) {
            float a[8], b[8];
            float4 a0 = *(const float4*)&As[k][ty * 4];
            float4 a1 = *(const float4*)&As[k][64 + ty * 4];
            a[0]=a0.x; a[1]=a0.y; a[2]=a0.z; a[3]=a0.w;
            a[4]=a1.x; a[5]=a1.y; a[6]=a1.z; a[7]=a1.w;
            float4 b0 = *(const float4*)&Bs[k][tx * 4];
            float4 b1 = *(const float4*)&Bs[k][64 + tx * 4];
            b[0]=b0.x; b[1]=b0.y; b[2]=b0.z; b[3]=b0.w;
            b[4]=b1.x; b[5]=b1.y; b[6]=b1.z; b[7]=b1.w;
#pragma unroll
            for (int i = 0; i < 8; i++)
#pragma unroll
                for (int j = 0; j < 8; j++)
                    acc[i][j] += a[i] * b[j];
        }
        __syncthreads();
    }

    // Epilogue: rows {row0+ty*4+i, row0+64+ty*4+i}, cols {col0+tx*4+j, col0+64+tx*4+j}
#pragma unroll
    for (int ig = 0; ig < 2; ig++) {
#pragma unroll
        for (int i = 0; i < 4; i++) {
            int r = row0 + ig * 64 + ty * 4 + i;
#pragma unroll
            for (int jg = 0; jg < 2; jg++) {
                int cb = col0 + jg * 64 + tx * 4;
                float4 o;
                o.x = acc[ig * 4 + i][jg * 4 + 0] + bias[cb + 0];
                o.y = acc[ig * 4 + i][jg * 4 + 1] + bias[cb + 1];
                o.z = acc[ig * 4 + i][jg * 4 + 2] + bias[cb + 2];
                o.w = acc[ig * 4 + i][jg * 4 + 3] + bias[cb + 3];
                *(float4*)(C + (size_t)r * N + cb) = o;
            }
        }
    }
}

// ---------------------------------------------------------------------------
// Flash attention (causal), head dim 16, one query per thread.
// grid: (16 q-tiles, 64 heads), 128 threads. K/V chunks of 64 rows in smem.
// qkv layout: row t has [q(1024) | k(1024) | v(1024)], head h at offset h*16.
// ---------------------------------------------------------------------------
__global__ __launch_bounds__(128) void attn_kernel(
    const float* __restrict__ qkv, float* __restrict__ attn_out)
{
    const int h     = blockIdx.y;
    const int qtile = blockIdx.x;
    const int tid   = threadIdx.x;
    const int qi    = qtile * 128 + tid;

    __shared__ float Ks[64][16];
    __shared__ float Vs[64][16];

    // load q row, pre-scale by 1/sqrt(16) = 0.25
    float q[16];
    {
        const float* qrow = qkv + (size_t)qi * (3 * C_EMB) + h * HDIM;
#pragma unroll
        for (int c = 0; c < 4; c++) {
            float4 v = *(const float4*)(qrow + c * 4);
            q[c*4+0] = v.x * 0.25f; q[c*4+1] = v.y * 0.25f;
            q[c*4+2] = v.z * 0.25f; q[c*4+3] = v.w * 0.25f;
        }
    }

    float acc[16];
#pragma unroll
    for (int d = 0; d < 16; d++) acc[d] = 0.f;
    float m = -3.0e38f, l = 0.f;

    const int kend = qtile * 128 + 128;   // causal bound for this block
    for (int k0 = 0; k0 < kend; k0 += 64) {
        // cooperative K/V chunk load: 64 rows x 4 float4, 2 per thread per array
#pragma unroll
        for (int i = tid; i < 256; i += 128) {
            int r  = i >> 2;
            int c4 = (i & 3) * 4;
            const float* kb = qkv + (size_t)(k0 + r) * (3 * C_EMB) + C_EMB + h * HDIM + c4;
            *(float4*)&Ks[r][c4] = *(const float4*)kb;
            *(float4*)&Vs[r][c4] = *(const float4*)(kb + C_EMB);
        }
        __syncthreads();

        float s[64];
#pragma unroll
        for (int j = 0; j < 64; j++) {
            float4 k0v = *(const float4*)&Ks[j][0];
            float4 k1v = *(const float4*)&Ks[j][4];
            float4 k2v = *(const float4*)&Ks[j][8];
            float4 k3v = *(const float4*)&Ks[j][12];
            float sv = q[0]*k0v.x + q[1]*k0v.y + q[2]*k0v.z + q[3]*k0v.w
                     + q[4]*k1v.x + q[5]*k1v.y + q[6]*k1v.z + q[7]*k1v.w
                     + q[8]*k2v.x + q[9]*k2v.y + q[10]*k2v.z + q[11]*k2v.w
                     + q[12]*k3v.x + q[13]*k3v.y + q[14]*k3v.z + q[15]*k3v.w;
            s[j] = (k0 + j <= qi) ? sv : -3.0e38f;
        }

        float cm = m;
#pragma unroll
        for (int j = 0; j < 64; j++) cm = fmaxf(cm, s[j]);
        float corr = __expf(m - cm);   // 0 on first chunk (m = -3e38), 1 if cm==m
        m = cm;
        l *= corr;
#pragma unroll
        for (int d = 0; d < 16; d++) acc[d] *= corr;

#pragma unroll
        for (int j = 0; j < 64; j++) {
            float p = __expf(s[j] - m);
            l += p;
            float4 v0 = *(const float4*)&Vs[j][0];
            float4 v1 = *(const float4*)&Vs[j][4];
            float4 v2 = *(const float4*)&Vs[j][8];
            float4 v3 = *(const float4*)&Vs[j][12];
            acc[0]  += p * v0.x; acc[1]  += p * v0.y; acc[2]  += p * v0.z; acc[3]  += p * v0.w;
            acc[4]  += p * v1.x; acc[5]  += p * v1.y; acc[6]  += p * v1.z; acc[7]  += p * v1.w;
            acc[8]  += p * v2.x; acc[9]  += p * v2.y; acc[10] += p * v2.z; acc[11] += p * v2.w;
            acc[12] += p * v3.x; acc[13] += p * v3.y; acc[14] += p * v3.z; acc[15] += p * v3.w;
        }
        __syncthreads();
    }

    float inv = 1.f / l;
    float* orow = attn_out + (size_t)qi * C_EMB + h * HDIM;
#pragma unroll
    for (int c = 0; c < 4; c++) {
        float4 o;
        o.x = acc[c*4+0] * inv; o.y = acc[c*4+1] * inv;
        o.z = acc[c*4+2] * inv; o.w = acc[c*4+3] * inv;
        *(float4*)(orow + c * 4) = o;
    }
}

// ---------------------------------------------------------------------------
// Launch
// ---------------------------------------------------------------------------
extern "C" void kernel_launch(void* const* d_in, const int* in_sizes, int n_in,
                              void* d_out, int out_size)
{
    const float* x     = (const float*)d_in[0];
    // d_in[1] = attn_mask (ignored; is_causal wins in the reference)
    const float* W_qkv = (const float*)d_in[2];
    const float* b_qkv = (const float*)d_in[3];
    const float* W_out = (const float*)d_in[4];
    const float* b_out = (const float*)d_in[5];
    float* out = (float*)d_out;

    float* qkv_buf = nullptr;
    float* attn_buf = nullptr;
    cudaGetSymbolAddress((void**)&qkv_buf, g_qkv);
    cudaGetSymbolAddress((void**)&attn_buf, g_attn);

    // 1) qkv = x @ W_qkv + b_qkv      [2048 x 3072]
    {
        dim3 grid(3 * C_EMB / 128, T_SEQ / 128);
        gemm_bias_kernel<<<grid, 256>>>(x, W_qkv, b_qkv, qkv_buf,
                                        T_SEQ, 3 * C_EMB, C_EMB);
    }

    // 2) causal attention -> attn_buf [2048 x 1024]
    {
        dim3 grid(T_SEQ / 128, NHEADS);
        attn_kernel<<<grid, 128>>>(qkv_buf, attn_buf);
    }

    // 3) out = attn @ W_out + b_out   [2048 x 1024]
    {
        dim3 grid(C_EMB / 128, T_SEQ / 128);
        gemm_bias_kernel<<<grid, 256>>>(attn_buf, W_out, b_out, out,
                                        T_SEQ, C_EMB, C_EMB);
    }
}

// round 2
// speedup vs baseline: 1.3441x; 1.3441x over previous
#include <cuda_runtime.h>
#include <cuda_bf16.h>
#include <cstdint>
#include <cstddef>

#define T_SEQ   2048
#define C_EMB   1024
#define HDIM    16
#define NHEADS  64

// Scratch (no cudaMalloc allowed)
__device__ float g_qkv[T_SEQ * 3 * C_EMB];
__device__ float g_attn[T_SEQ * C_EMB];

// ---------------------------------------------------------------------------
// TF32 tensor-core GEMM: C[M,N] = A[M,K] @ B[K,N] + bias[N]
// 128x128 block, BK=16, 256 threads = 8 warps (4 along M x 2 along N),
// warp tile 32x64 via mma.sync.m16n8k8 tf32. Smem padded +8 floats so all
// fragment LDS are bank-conflict-free (bank = (8k + m) % 32 is a permutation
// over the warp's (t4, g) lanes).
// ---------------------------------------------------------------------------
__global__ __launch_bounds__(256) void gemm_tf32_bias_kernel(
    const float* __restrict__ A, const float* __restrict__ B,
    const float* __restrict__ bias, float* __restrict__ C,
    int M, int N, int K)
{
    __shared__ float As[16][136];   // [k][m], padded
    __shared__ float Bs[16][136];   // [k][n], padded

    const int tid  = threadIdx.x;
    const int lane = tid & 31;
    const int warp = tid >> 5;
    const int wm   = (warp & 3) * 32;
    const int wn   = (warp >> 2) * 64;
    const int g    = lane >> 2;     // 0..7
    const int t4   = lane & 3;      // 0..3
    const int row0 = blockIdx.y * 128;
    const int col0 = blockIdx.x * 128;

    float acc[2][8][4];
#pragma unroll
    for (int ms = 0; ms < 2; ms++)
#pragma unroll
        for (int ns = 0; ns < 8; ns++)
#pragma unroll
            for (int i = 0; i < 4; i++) acc[ms][ns][i] = 0.f;

    for (int k0 = 0; k0 < K; k0 += 16) {
        // --- load A tile 128x16, transpose into As[k][m] with tf32 rounding
#pragma unroll
        for (int it = 0; it < 2; it++) {
            int lin = tid + it * 256;          // 0..511
            int r   = lin >> 2;                // 0..127
            int kc  = (lin & 3) * 4;           // 0,4,8,12
            float4 v = *(const float4*)(A + (size_t)(row0 + r) * K + k0 + kc);
            uint32_t u0, u1, u2, u3;
            asm("cvt.rna.tf32.f32 %0, %1;" : "=r"(u0) : "f"(v.x));
            asm("cvt.rna.tf32.f32 %0, %1;" : "=r"(u1) : "f"(v.y));
            asm("cvt.rna.tf32.f32 %0, %1;" : "=r"(u2) : "f"(v.z));
            asm("cvt.rna.tf32.f32 %0, %1;" : "=r"(u3) : "f"(v.w));
            As[kc + 0][r] = __uint_as_float(u0);
            As[kc + 1][r] = __uint_as_float(u1);
            As[kc + 2][r] = __uint_as_float(u2);
            As[kc + 3][r] = __uint_as_float(u3);
        }
        // --- load B tile 16x128 into Bs[k][n] with tf32 rounding
#pragma unroll
        for (int it = 0; it < 2; it++) {
            int lin = tid + it * 256;
            int r   = lin >> 5;                // 0..15
            int c4  = (lin & 31) * 4;          // 0..124
            float4 v = *(const float4*)(B + (size_t)(k0 + r) * N + col0 + c4);
            uint32_t u0, u1, u2, u3;
            asm("cvt.rna.tf32.f32 %0, %1;" : "=r"(u0) : "f"(v.x));
            asm("cvt.rna.tf32.f32 %0, %1;" : "=r"(u1) : "f"(v.y));
            asm("cvt.rna.tf32.f32 %0, %1;" : "=r"(u2) : "f"(v.z));
            asm("cvt.rna.tf32.f32 %0, %1;" : "=r"(u3) : "f"(v.w));
            float4 o;
            o.x = __uint_as_float(u0); o.y = __uint_as_float(u1);
            o.z = __uint_as_float(u2); o.w = __uint_as_float(u3);
            *(float4*)&Bs[r][c4] = o;
        }
        __syncthreads();

#pragma unroll
        for (int kk = 0; kk < 16; kk += 8) {
            uint32_t af[2][4];
#pragma unroll
            for (int ms = 0; ms < 2; ms++) {
                af[ms][0] = __float_as_uint(As[kk + t4    ][wm + ms * 16 + g    ]);
                af[ms][1] = __float_as_uint(As[kk + t4    ][wm + ms * 16 + g + 8]);
                af[ms][2] = __float_as_uint(As[kk + t4 + 4][wm + ms * 16 + g    ]);
                af[ms][3] = __float_as_uint(As[kk + t4 + 4][wm + ms * 16 + g + 8]);
            }
            uint32_t bf[8][2];
#pragma unroll
            for (int ns = 0; ns < 8; ns++) {
                bf[ns][0] = __float_as_uint(Bs[kk + t4    ][wn + ns * 8 + g]);
                bf[ns][1] = __float_as_uint(Bs[kk + t4 + 4][wn + ns * 8 + g]);
            }
#pragma unroll
            for (int ms = 0; ms < 2; ms++)
#pragma unroll
                for (int ns = 0; ns < 8; ns++) {
                    float* c = acc[ms][ns];
                    asm volatile(
                        "mma.sync.aligned.m16n8k8.row.col.f32.tf32.tf32.f32 "
                        "{%0,%1,%2,%3}, {%4,%5,%6,%7}, {%8,%9}, {%0,%1,%2,%3};"
                        : "+f"(c[0]), "+f"(c[1]), "+f"(c[2]), "+f"(c[3])
                        : "r"(af[ms][0]), "r"(af[ms][1]),
                          "r"(af[ms][2]), "r"(af[ms][3]),
                          "r"(bf[ns][0]), "r"(bf[ns][1]));
                }
        }
        __syncthreads();
    }

    // Epilogue: c0/c1 at (g, 2*t4, +1), c2/c3 at (g+8, same cols)
#pragma unroll
    for (int ms = 0; ms < 2; ms++) {
#pragma unroll
        for (int ns = 0; ns < 8; ns++) {
            int r = row0 + wm + ms * 16 + g;
            int c = col0 + wn + ns * 8 + t4 * 2;
            float2 bv = *(const float2*)(bias + c);
            float2 o0, o1;
            o0.x = acc[ms][ns][0] + bv.x; o0.y = acc[ms][ns][1] + bv.y;
            o1.x = acc[ms][ns][2] + bv.x; o1.y = acc[ms][ns][3] + bv.y;
            *(float2*)(C + (size_t)r * N + c) = o0;
            *(float2*)(C + (size_t)(r + 8) * N + c) = o1;
        }
    }
}

// ---------------------------------------------------------------------------
// Flash attention (causal), head dim 16, one query per thread.
// K/V chunks of 64 rows in smem; scores processed in two 32-wide halves to
// keep live registers ~90 (s[32] instead of s[64]).
// ---------------------------------------------------------------------------
__global__ __launch_bounds__(128) void attn_kernel(
    const float* __restrict__ qkv, float* __restrict__ attn_out)
{
    const int h     = blockIdx.y;
    const int qtile = blockIdx.x;
    const int tid   = threadIdx.x;
    const int qi    = qtile * 128 + tid;

    __shared__ float Ks[64][16];
    __shared__ float Vs[64][16];

    float q[16];
    {
        const float* qrow = qkv + (size_t)qi * (3 * C_EMB) + h * HDIM;
#pragma unroll
        for (int c = 0; c < 4; c++) {
            float4 v = *(const float4*)(qrow + c * 4);
            q[c*4+0] = v.x * 0.25f; q[c*4+1] = v.y * 0.25f;
            q[c*4+2] = v.z * 0.25f; q[c*4+3] = v.w * 0.25f;
        }
    }

    float acc[16];
#pragma unroll
    for (int d = 0; d < 16; d++) acc[d] = 0.f;
    float m = -3.0e38f, l = 0.f;

    const int kend = qtile * 128 + 128;
    for (int k0 = 0; k0 < kend; k0 += 64) {
#pragma unroll
        for (int i = tid; i < 256; i += 128) {
            int r  = i >> 2;
            int c4 = (i & 3) * 4;
            const float* kb = qkv + (size_t)(k0 + r) * (3 * C_EMB) + C_EMB + h * HDIM + c4;
            *(float4*)&Ks[r][c4] = *(const float4*)kb;
            *(float4*)&Vs[r][c4] = *(const float4*)(kb + C_EMB);
        }
        __syncthreads();

#pragma unroll
        for (int half = 0; half < 2; half++) {
            const int base = half * 32;
            float s[32];
#pragma unroll
            for (int j = 0; j < 32; j++) {
                int jj = base + j;
                float4 k0v = *(const float4*)&Ks[jj][0];
                float4 k1v = *(const float4*)&Ks[jj][4];
                float4 k2v = *(const float4*)&Ks[jj][8];
                float4 k3v = *(const float4*)&Ks[jj][12];
                float sv = q[0]*k0v.x + q[1]*k0v.y + q[2]*k0v.z + q[3]*k0v.w
                         + q[4]*k1v.x + q[5]*k1v.y + q[6]*k1v.z + q[7]*k1v.w
                         + q[8]*k2v.x + q[9]*k2v.y + q[10]*k2v.z + q[11]*k2v.w
                         + q[12]*k3v.x + q[13]*k3v.y + q[14]*k3v.z + q[15]*k3v.w;
                s[j] = (k0 + jj <= qi) ? sv : -3.0e38f;
            }

            float cm = m;
#pragma unroll
            for (int j = 0; j < 32; j++) cm = fmaxf(cm, s[j]);
            float corr = __expf(m - cm);    // 0 on first half (m=-3e38), else <=1
            m = cm;
            l *= corr;
#pragma unroll
            for (int d = 0; d < 16; d++) acc[d] *= corr;

#pragma unroll
            for (int j = 0; j < 32; j++) {
                int jj = base + j;
                float p = __expf(s[j] - m);
                l += p;
                float4 v0 = *(const float4*)&Vs[jj][0];
                float4 v1 = *(const float4*)&Vs[jj][4];
                float4 v2 = *(const float4*)&Vs[jj][8];
                float4 v3 = *(const float4*)&Vs[jj][12];
                acc[0]  += p * v0.x; acc[1]  += p * v0.y; acc[2]  += p * v0.z; acc[3]  += p * v0.w;
                acc[4]  += p * v1.x; acc[5]  += p * v1.y; acc[6]  += p * v1.z; acc[7]  += p * v1.w;
                acc[8]  += p * v2.x; acc[9]  += p * v2.y; acc[10] += p * v2.z; acc[11] += p * v2.w;
                acc[12] += p * v3.x; acc[13] += p * v3.y; acc[14] += p * v3.z; acc[15] += p * v3.w;
            }
        }
        __syncthreads();
    }

    float inv = 1.f / l;
    float* orow = attn_out + (size_t)qi * C_EMB + h * HDIM;
#pragma unroll
    for (int c = 0; c < 4; c++) {
        float4 o;
        o.x = acc[c*4+0] * inv; o.y = acc[c*4+1] * inv;
        o.z = acc[c*4+2] * inv; o.w = acc[c*4+3] * inv;
        *(float4*)(orow + c * 4) = o;
    }
}

// ---------------------------------------------------------------------------
// Launch
// ---------------------------------------------------------------------------
extern "C" void kernel_launch(void* const* d_in, const int* in_sizes, int n_in,
                              void* d_out, int out_size)
{
    const float* x     = (const float*)d_in[0];
    // d_in[1] = attn_mask (ignored; is_causal wins in the reference)
    const float* W_qkv = (const float*)d_in[2];
    const float* b_qkv = (const float*)d_in[3];
    const float* W_out = (const float*)d_in[4];
    const float* b_out = (const float*)d_in[5];
    float* out = (float*)d_out;

    float* qkv_buf = nullptr;
    float* attn_buf = nullptr;
    cudaGetSymbolAddress((void**)&qkv_buf, g_qkv);
    cudaGetSymbolAddress((void**)&attn_buf, g_attn);

    // 1) qkv = x @ W_qkv + b_qkv      [2048 x 3072]
    {
        dim3 grid(3 * C_EMB / 128, T_SEQ / 128);
        gemm_tf32_bias_kernel<<<grid, 256>>>(x, W_qkv, b_qkv, qkv_buf,
                                             T_SEQ, 3 * C_EMB, C_EMB);
    }

    // 2) causal attention -> attn_buf [2048 x 1024]
    {
        dim3 grid(T_SEQ / 128, NHEADS);
        attn_kernel<<<grid, 128>>>(qkv_buf, attn_buf);
    }

    // 3) out = attn @ W_out + b_out   [2048 x 1024]
    {
        dim3 grid(C_EMB / 128, T_SEQ / 128);
        gemm_tf32_bias_kernel<<<grid, 256>>>(attn_buf, W_out, b_out, out,
                                             T_SEQ, C_EMB, C_EMB);
    }
}

// round 3
// speedup vs baseline: 1.8016x; 1.3404x over previous
#include <cuda_runtime.h>
#include <cuda_bf16.h>
#include <cstdint>
#include <cstddef>

#define T_SEQ   2048
#define C_EMB   1024
#define HDIM    16
#define NHEADS  64

// Scratch (no cudaMalloc allowed)
__device__ float g_qkv[T_SEQ * 3 * C_EMB];
__device__ float g_attn[T_SEQ * C_EMB];

__device__ __forceinline__ uint32_t f2tf32(float x) {
    uint32_t u;
    asm("cvt.rna.tf32.f32 %0, %1;" : "=r"(u) : "f"(x));
    return u;
}
__device__ __forceinline__ float u2f(uint32_t u) { return __uint_as_float(u); }

__device__ __forceinline__ void mma_tf32(float c[4], const uint32_t a[4],
                                         uint32_t b0, uint32_t b1) {
    asm volatile(
        "mma.sync.aligned.m16n8k8.row.col.f32.tf32.tf32.f32 "
        "{%0,%1,%2,%3}, {%4,%5,%6,%7}, {%8,%9}, {%0,%1,%2,%3};"
        : "+f"(c[0]), "+f"(c[1]), "+f"(c[2]), "+f"(c[3])
        : "r"(a[0]), "r"(a[1]), "r"(a[2]), "r"(a[3]), "r"(b0), "r"(b1));
}

#define CP_ASYNC16(dst, src) \
    asm volatile("cp.async.cg.shared.global [%0], [%1], 16;" :: "r"(dst), "l"(src))
#define CP_COMMIT() asm volatile("cp.async.commit_group;")
#define CP_WAIT(n)  asm volatile("cp.async.wait_group %0;" :: "n"(n))

// ---------------------------------------------------------------------------
// TF32 GEMM with 2-stage cp.async pipeline: C = A @ B + bias
// 128x128 block, BK=16, 256 threads (8 warps: 4xM, 2xN), warp tile 32x64.
// As[m][k] pad->20 floats, Bs[k][n] pad->136 floats: conflict-free frag LDS.
// tf32 cvt (rna) applied at fragment-load time.
// ---------------------------------------------------------------------------
__global__ __launch_bounds__(256, 2) void gemm_tf32_bias_kernel(
    const float* __restrict__ A, const float* __restrict__ B,
    const float* __restrict__ bias, float* __restrict__ C,
    int M, int N, int K)
{
    __shared__ float As[2][128][20];
    __shared__ float Bs[2][16][136];

    const int tid  = threadIdx.x;
    const int lane = tid & 31;
    const int warp = tid >> 5;
    const int wm   = (warp & 3) * 32;
    const int wn   = (warp >> 2) * 64;
    const int g    = lane >> 2;
    const int t4   = lane & 3;
    const int row0 = blockIdx.y * 128;
    const int col0 = blockIdx.x * 128;

    float acc[2][8][4];
#pragma unroll
    for (int ms = 0; ms < 2; ms++)
#pragma unroll
        for (int ns = 0; ns < 8; ns++)
#pragma unroll
            for (int i = 0; i < 4; i++) acc[ms][ns][i] = 0.f;

    // load-index precompute
    const int a_r  = (tid * 2) >> 2;            // unused; keep simple below

    auto issue_loads = [&](int k0, int st) {
#pragma unroll
        for (int it = 0; it < 2; it++) {
            int lin = tid + it * 256;           // 0..511
            int r   = lin >> 2;                 // 0..127
            int kc  = (lin & 3) * 4;
            uint32_t dst = (uint32_t)__cvta_generic_to_shared(&As[st][r][kc]);
            CP_ASYNC16(dst, A + (size_t)(row0 + r) * K + k0 + kc);
        }
#pragma unroll
        for (int it = 0; it < 2; it++) {
            int lin = tid + it * 256;
            int r   = lin >> 5;                 // 0..15
            int c4  = (lin & 31) * 4;
            uint32_t dst = (uint32_t)__cvta_generic_to_shared(&Bs[st][r][c4]);
            CP_ASYNC16(dst, B + (size_t)(k0 + r) * N + col0 + c4);
        }
    };

    const int niter = K / 16;
    issue_loads(0, 0);
    CP_COMMIT();

    for (int i = 0; i < niter; i++) {
        if (i + 1 < niter) {
            issue_loads((i + 1) * 16, (i + 1) & 1);
            CP_COMMIT();
            CP_WAIT(1);
        } else {
            CP_WAIT(0);
        }
        __syncthreads();

        const int st = i & 1;
#pragma unroll
        for (int kk = 0; kk < 16; kk += 8) {
            uint32_t af[2][4];
#pragma unroll
            for (int ms = 0; ms < 2; ms++) {
                af[ms][0] = f2tf32(As[st][wm + ms * 16 + g    ][kk + t4    ]);
                af[ms][1] = f2tf32(As[st][wm + ms * 16 + g + 8][kk + t4    ]);
                af[ms][2] = f2tf32(As[st][wm + ms * 16 + g    ][kk + t4 + 4]);
                af[ms][3] = f2tf32(As[st][wm + ms * 16 + g + 8][kk + t4 + 4]);
            }
            uint32_t bf[8][2];
#pragma unroll
            for (int ns = 0; ns < 8; ns++) {
                bf[ns][0] = f2tf32(Bs[st][kk + t4    ][wn + ns * 8 + g]);
                bf[ns][1] = f2tf32(Bs[st][kk + t4 + 4][wn + ns * 8 + g]);
            }
#pragma unroll
            for (int ms = 0; ms < 2; ms++)
#pragma unroll
                for (int ns = 0; ns < 8; ns++)
                    mma_tf32(acc[ms][ns], af[ms], bf[ns][0], bf[ns][1]);
        }
        __syncthreads();
    }

#pragma unroll
    for (int ms = 0; ms < 2; ms++) {
#pragma unroll
        for (int ns = 0; ns < 8; ns++) {
            int r = row0 + wm + ms * 16 + g;
            int c = col0 + wn + ns * 8 + t4 * 2;
            float2 bv = *(const float2*)(bias + c);
            float2 o0, o1;
            o0.x = acc[ms][ns][0] + bv.x; o0.y = acc[ms][ns][1] + bv.y;
            o1.x = acc[ms][ns][2] + bv.x; o1.y = acc[ms][ns][3] + bv.y;
            *(float2*)(C + (size_t)r * N + c) = o0;
            *(float2*)(C + (size_t)(r + 8) * N + c) = o1;
        }
    }
}

// ---------------------------------------------------------------------------
// Tensor-core flash attention (causal), 64 heads x dim 16.
// Block: 1 head x 64 q-rows, 4 warps (16 q-rows each). Key chunks of 64.
// Scores: mma tf32 (Q frags in regs, K^T frags from smem).
// Online softmax on fragments (shfl over t4 lanes per row).
// P -> per-warp smem tile (C-layout -> A-layout), P@V: mma tf32.
// ---------------------------------------------------------------------------
__global__ __launch_bounds__(128) void attn_tc_kernel(
    const float* __restrict__ qkv, float* __restrict__ attn_out)
{
    __shared__ float Ks[64][20];        // [key][dim], pad 20
    __shared__ float Vs[64][24];        // [key][dim], pad 24
    __shared__ float Ps[4][16][68];     // per-warp P tile [qrow][key], pad 68

    const int h    = blockIdx.y;
    const int qt   = (int)gridDim.x - 1 - (int)blockIdx.x;  // heavy tiles first
    const int tid  = threadIdx.x;
    const int lane = tid & 31;
    const int w    = tid >> 5;
    const int g    = lane >> 2;
    const int t4   = lane & 3;
    const int qbase = qt * 64 + w * 16;

    // Q fragments (scaled by 1/sqrt(16) = 0.25), rows qbase+g / qbase+g+8
    uint32_t qa[2][4];
    {
        const float* qp = qkv + (size_t)qbase * (3 * C_EMB) + h * HDIM;
#pragma unroll
        for (int kt = 0; kt < 2; kt++) {
            qa[kt][0] = f2tf32(qp[(size_t)g       * (3 * C_EMB) + kt * 8 + t4    ] * 0.25f);
            qa[kt][1] = f2tf32(qp[(size_t)(g + 8) * (3 * C_EMB) + kt * 8 + t4    ] * 0.25f);
            qa[kt][2] = f2tf32(qp[(size_t)g       * (3 * C_EMB) + kt * 8 + t4 + 4] * 0.25f);
            qa[kt][3] = f2tf32(qp[(size_t)(g + 8) * (3 * C_EMB) + kt * 8 + t4 + 4] * 0.25f);
        }
    }

    float o[2][4];
#pragma unroll
    for (int nt = 0; nt < 2; nt++)
#pragma unroll
        for (int i = 0; i < 4; i++) o[nt][i] = 0.f;
    float m0 = -1e30f, m1 = -1e30f, l0 = 0.f, l1 = 0.f;

    const int nch = qt + 1;
    for (int ci = 0; ci < nch; ci++) {
        const int k0 = ci * 64;
        __syncthreads();    // all warps done with previous Ks/Vs (and Ps reads)

        // cooperative K/V chunk load (+ tf32 cvt), 2 float4 per thread each
#pragma unroll
        for (int it = 0; it < 2; it++) {
            int lin = tid + it * 128;
            int key = lin >> 2;
            int c4  = (lin & 3) * 4;
            const float* kp = qkv + (size_t)(k0 + key) * (3 * C_EMB) + C_EMB + h * HDIM + c4;
            float4 kv = *(const float4*)kp;
            float4 vv = *(const float4*)(kp + C_EMB);
            float4 kc, vc;
            kc.x = u2f(f2tf32(kv.x)); kc.y = u2f(f2tf32(kv.y));
            kc.z = u2f(f2tf32(kv.z)); kc.w = u2f(f2tf32(kv.w));
            vc.x = u2f(f2tf32(vv.x)); vc.y = u2f(f2tf32(vv.y));
            vc.z = u2f(f2tf32(vv.z)); vc.w = u2f(f2tf32(vv.w));
            *(float4*)&Ks[key][c4] = kc;
            *(float4*)&Vs[key][c4] = vc;
        }
        __syncthreads();

        // scores S = Q @ K^T  (16 x 64 per warp)
        float sf[8][4];
#pragma unroll
        for (int ns = 0; ns < 8; ns++) {
            sf[ns][0] = 0.f; sf[ns][1] = 0.f; sf[ns][2] = 0.f; sf[ns][3] = 0.f;
#pragma unroll
            for (int kt = 0; kt < 2; kt++) {
                uint32_t b0 = __float_as_uint(Ks[ns * 8 + g][kt * 8 + t4    ]);
                uint32_t b1 = __float_as_uint(Ks[ns * 8 + g][kt * 8 + t4 + 4]);
                mma_tf32(sf[ns], qa[kt], b0, b1);
            }
        }

        // causal mask (only the diagonal chunk needs it)
        if (k0 + 63 > qbase) {
            const int r0 = qbase + g, r1 = r0 + 8;
#pragma unroll
            for (int ns = 0; ns < 8; ns++) {
                int col = k0 + ns * 8 + 2 * t4;
                if (col     > r0) sf[ns][0] = -1e30f;
                if (col + 1 > r0) sf[ns][1] = -1e30f;
                if (col     > r1) sf[ns][2] = -1e30f;
                if (col + 1 > r1) sf[ns][3] = -1e30f;
            }
        }

        // row max (per-thread partial, then shfl over t4 lanes)
        float rm0 = -1e30f, rm1 = -1e30f;
#pragma unroll
        for (int ns = 0; ns < 8; ns++) {
            rm0 = fmaxf(rm0, fmaxf(sf[ns][0], sf[ns][1]));
            rm1 = fmaxf(rm1, fmaxf(sf[ns][2], sf[ns][3]));
        }
        rm0 = fmaxf(rm0, __shfl_xor_sync(0xffffffffu, rm0, 1));
        rm0 = fmaxf(rm0, __shfl_xor_sync(0xffffffffu, rm0, 2));
        rm1 = fmaxf(rm1, __shfl_xor_sync(0xffffffffu, rm1, 1));
        rm1 = fmaxf(rm1, __shfl_xor_sync(0xffffffffu, rm1, 2));

        float nm0 = fmaxf(m0, rm0), nm1 = fmaxf(m1, rm1);
        float corr0 = __expf(m0 - nm0), corr1 = __expf(m1 - nm1);
        m0 = nm0; m1 = nm1;
        l0 *= corr0; l1 *= corr1;
#pragma unroll
        for (int nt = 0; nt < 2; nt++) {
            o[nt][0] *= corr0; o[nt][1] *= corr0;
            o[nt][2] *= corr1; o[nt][3] *= corr1;
        }

        // p = exp(s - m), accumulate l, stage tf32 P into per-warp smem
#pragma unroll
        for (int ns = 0; ns < 8; ns++) {
            float p0 = __expf(sf[ns][0] - m0);
            float p1 = __expf(sf[ns][1] - m0);
            float p2 = __expf(sf[ns][2] - m1);
            float p3 = __expf(sf[ns][3] - m1);
            l0 += p0 + p1;
            l1 += p2 + p3;
            float2 v01, v23;
            v01.x = u2f(f2tf32(p0)); v01.y = u2f(f2tf32(p1));
            v23.x = u2f(f2tf32(p2)); v23.y = u2f(f2tf32(p3));
            *(float2*)&Ps[w][g    ][ns * 8 + 2 * t4] = v01;
            *(float2*)&Ps[w][g + 8][ns * 8 + 2 * t4] = v23;
        }
        __syncwarp();

        // O += P @ V
#pragma unroll
        for (int kt = 0; kt < 8; kt++) {
            uint32_t pa[4];
            pa[0] = __float_as_uint(Ps[w][g    ][kt * 8 + t4    ]);
            pa[1] = __float_as_uint(Ps[w][g + 8][kt * 8 + t4    ]);
            pa[2] = __float_as_uint(Ps[w][g    ][kt * 8 + t4 + 4]);
            pa[3] = __float_as_uint(Ps[w][g + 8][kt * 8 + t4 + 4]);
#pragma unroll
            for (int nt = 0; nt < 2; nt++) {
                uint32_t b0 = __float_as_uint(Vs[kt * 8 + t4    ][nt * 8 + g]);
                uint32_t b1 = __float_as_uint(Vs[kt * 8 + t4 + 4][nt * 8 + g]);
                mma_tf32(o[nt], pa, b0, b1);
            }
        }
    }

    // finalize: reduce l over t4 lanes, normalize, store
    l0 += __shfl_xor_sync(0xffffffffu, l0, 1);
    l0 += __shfl_xor_sync(0xffffffffu, l0, 2);
    l1 += __shfl_xor_sync(0xffffffffu, l1, 1);
    l1 += __shfl_xor_sync(0xffffffffu, l1, 2);
    const float inv0 = 1.f / l0, inv1 = 1.f / l1;

    float* op = attn_out + (size_t)qbase * C_EMB + h * HDIM;
#pragma unroll
    for (int nt = 0; nt < 2; nt++) {
        float2 o0, o1;
        o0.x = o[nt][0] * inv0; o0.y = o[nt][1] * inv0;
        o1.x = o[nt][2] * inv1; o1.y = o[nt][3] * inv1;
        *(float2*)&op[(size_t)g       * C_EMB + nt * 8 + 2 * t4] = o0;
        *(float2*)&op[(size_t)(g + 8) * C_EMB + nt * 8 + 2 * t4] = o1;
    }
}

// ---------------------------------------------------------------------------
// Launch
// ---------------------------------------------------------------------------
extern "C" void kernel_launch(void* const* d_in, const int* in_sizes, int n_in,
                              void* d_out, int out_size)
{
    const float* x     = (const float*)d_in[0];
    // d_in[1] = attn_mask (ignored; is_causal wins in the reference)
    const float* W_qkv = (const float*)d_in[2];
    const float* b_qkv = (const float*)d_in[3];
    const float* W_out = (const float*)d_in[4];
    const float* b_out = (const float*)d_in[5];
    float* out = (float*)d_out;

    float* qkv_buf = nullptr;
    float* attn_buf = nullptr;
    cudaGetSymbolAddress((void**)&qkv_buf, g_qkv);
    cudaGetSymbolAddress((void**)&attn_buf, g_attn);

    // 1) qkv = x @ W_qkv + b_qkv      [2048 x 3072]
    {
        dim3 grid(3 * C_EMB / 128, T_SEQ / 128);
        gemm_tf32_bias_kernel<<<grid, 256>>>(x, W_qkv, b_qkv, qkv_buf,
                                             T_SEQ, 3 * C_EMB, C_EMB);
    }

    // 2) causal attention -> attn_buf [2048 x 1024]
    {
        dim3 grid(T_SEQ / 64, NHEADS);
        attn_tc_kernel<<<grid, 128>>>(qkv_buf, attn_buf);
    }

    // 3) out = attn @ W_out + b_out   [2048 x 1024]
    {
        dim3 grid(C_EMB / 128, T_SEQ / 128);
        gemm_tf32_bias_kernel<<<grid, 256>>>(attn_buf, W_out, b_out, out,
                                             T_SEQ, C_EMB, C_EMB);
    }
}

// round 4
// speedup vs baseline: 2.7647x; 1.5346x over previous
#include <cuda_runtime.h>
#include <cuda_bf16.h>
#include <cstdint>
#include <cstddef>

#define T_SEQ   2048
#define C_EMB   1024
#define HDIM    16
#define NHEADS  64

// Scratch (no cudaMalloc allowed)
__device__ float g_qkv[T_SEQ * 3 * C_EMB];
__device__ float g_attn[T_SEQ * C_EMB];
__device__ float g_x[T_SEQ * C_EMB];
__device__ float g_wqkv[C_EMB * 3 * C_EMB];
__device__ float g_wout[C_EMB * C_EMB];

__device__ __forceinline__ uint32_t f2tf32(float x) {
    uint32_t u;
    asm("cvt.rna.tf32.f32 %0, %1;" : "=r"(u) : "f"(x));
    return u;
}
__device__ __forceinline__ float u2f(uint32_t u) { return __uint_as_float(u); }

__device__ __forceinline__ void mma_tf32(float c[4], const uint32_t a[4],
                                         uint32_t b0, uint32_t b1) {
    asm volatile(
        "mma.sync.aligned.m16n8k8.row.col.f32.tf32.tf32.f32 "
        "{%0,%1,%2,%3}, {%4,%5,%6,%7}, {%8,%9}, {%0,%1,%2,%3};"
        : "+f"(c[0]), "+f"(c[1]), "+f"(c[2]), "+f"(c[3])
        : "r"(a[0]), "r"(a[1]), "r"(a[2]), "r"(a[3]), "r"(b0), "r"(b1));
}

#define CP_ASYNC16(dst, src) \
    asm volatile("cp.async.cg.shared.global [%0], [%1], 16;" :: "r"(dst), "l"(src))
#define CP_COMMIT() asm volatile("cp.async.commit_group;")
#define CP_WAIT(n)  asm volatile("cp.async.wait_group %0;" :: "n"(n))

// ---------------------------------------------------------------------------
// Elementwise tf32 rounding (prologue): out[i] = tf32(in[i])
// ---------------------------------------------------------------------------
__global__ void cvt_tf32_kernel(const float* __restrict__ in,
                                float* __restrict__ out, int n4)
{
    int i = blockIdx.x * blockDim.x + threadIdx.x;
    if (i >= n4) return;
    float4 v = ((const float4*)in)[i];
    float4 o;
    o.x = u2f(f2tf32(v.x)); o.y = u2f(f2tf32(v.y));
    o.z = u2f(f2tf32(v.z)); o.w = u2f(f2tf32(v.w));
    ((float4*)out)[i] = o;
}

// ---------------------------------------------------------------------------
// TF32 GEMM, inputs pre-rounded to tf32. C = A @ B + bias, optional tf32
// rounding of C. 128x128 block, BK=16, 8 warps (4xM, 2xN), warp tile 32x64.
// Single-barrier 2-stage cp.async pipeline.
// ---------------------------------------------------------------------------
template <bool ROUND_OUT>
__global__ __launch_bounds__(256, 2) void gemm_tf32_bias_kernel(
    const float* __restrict__ A, const float* __restrict__ B,
    const float* __restrict__ bias, float* __restrict__ C,
    int M, int N, int K)
{
    __shared__ __align__(16) float As[2][128][20];
    __shared__ __align__(16) float Bs[2][16][136];

    const int tid  = threadIdx.x;
    const int lane = tid & 31;
    const int warp = tid >> 5;
    const int wm   = (warp & 3) * 32;
    const int wn   = (warp >> 2) * 64;
    const int g    = lane >> 2;
    const int t4   = lane & 3;
    const int row0 = blockIdx.y * 128;
    const int col0 = blockIdx.x * 128;

    float acc[2][8][4];
#pragma unroll
    for (int ms = 0; ms < 2; ms++)
#pragma unroll
        for (int ns = 0; ns < 8; ns++)
#pragma unroll
            for (int i = 0; i < 4; i++) acc[ms][ns][i] = 0.f;

    // per-thread load coordinates
    const int ar = tid >> 1;                  // 0..127 (two k-segments per row)
    const int ak = (tid & 1) * 8;             // 0 or 8 (two float4 below)
    const int br = tid >> 5;                  // 0..7  (two rows below)
    const int bc = (tid & 31) * 4;            // 0..124

    auto issue_loads = [&](int k0, int st) {
        const float* ap = A + (size_t)(row0 + ar) * K + k0 + ak;
        CP_ASYNC16((uint32_t)__cvta_generic_to_shared(&As[st][ar][ak    ]), ap);
        CP_ASYNC16((uint32_t)__cvta_generic_to_shared(&As[st][ar][ak + 4]), ap + 4);
        const float* bp = B + (size_t)(k0 + br) * N + col0 + bc;
        CP_ASYNC16((uint32_t)__cvta_generic_to_shared(&Bs[st][br    ][bc]), bp);
        CP_ASYNC16((uint32_t)__cvta_generic_to_shared(&Bs[st][br + 8][bc]),
                   bp + (size_t)8 * N);
    };

    const int niter = K / 16;
    issue_loads(0, 0);
    CP_COMMIT();

    for (int i = 0; i < niter; i++) {
        CP_WAIT(0);
        __syncthreads();
        if (i + 1 < niter) {
            issue_loads((i + 1) * 16, (i + 1) & 1);
            CP_COMMIT();
        }
        const int st = i & 1;
#pragma unroll
        for (int kk = 0; kk < 16; kk += 8) {
            uint32_t af[2][4];
#pragma unroll
            for (int ms = 0; ms < 2; ms++) {
                af[ms][0] = __float_as_uint(As[st][wm + ms * 16 + g    ][kk + t4    ]);
                af[ms][1] = __float_as_uint(As[st][wm + ms * 16 + g + 8][kk + t4    ]);
                af[ms][2] = __float_as_uint(As[st][wm + ms * 16 + g    ][kk + t4 + 4]);
                af[ms][3] = __float_as_uint(As[st][wm + ms * 16 + g + 8][kk + t4 + 4]);
            }
            uint32_t bf[8][2];
#pragma unroll
            for (int ns = 0; ns < 8; ns++) {
                bf[ns][0] = __float_as_uint(Bs[st][kk + t4    ][wn + ns * 8 + g]);
                bf[ns][1] = __float_as_uint(Bs[st][kk + t4 + 4][wn + ns * 8 + g]);
            }
#pragma unroll
            for (int ms = 0; ms < 2; ms++)
#pragma unroll
                for (int ns = 0; ns < 8; ns++)
                    mma_tf32(acc[ms][ns], af[ms], bf[ns][0], bf[ns][1]);
        }
        __syncthreads();
    }

#pragma unroll
    for (int ms = 0; ms < 2; ms++) {
#pragma unroll
        for (int ns = 0; ns < 8; ns++) {
            int r = row0 + wm + ms * 16 + g;
            int c = col0 + wn + ns * 8 + t4 * 2;
            float2 bv = *(const float2*)(bias + c);
            float2 o0, o1;
            o0.x = acc[ms][ns][0] + bv.x; o0.y = acc[ms][ns][1] + bv.y;
            o1.x = acc[ms][ns][2] + bv.x; o1.y = acc[ms][ns][3] + bv.y;
            if (ROUND_OUT) {
                o0.x = u2f(f2tf32(o0.x)); o0.y = u2f(f2tf32(o0.y));
                o1.x = u2f(f2tf32(o1.x)); o1.y = u2f(f2tf32(o1.y));
            }
            *(float2*)(C + (size_t)r * N + c) = o0;
            *(float2*)(C + (size_t)(r + 8) * N + c) = o1;
        }
    }
}

// ---------------------------------------------------------------------------
// Tensor-core flash attention (causal), 64 heads x dim 16.
// Block: 1 head x 64 q-rows, 4 warps (16 q-rows each). 64-key chunks,
// cp.async double-buffered, one __syncthreads per chunk. Inputs already
// tf32-rounded; outputs rounded to tf32 for the projection GEMM.
// ---------------------------------------------------------------------------
__global__ __launch_bounds__(128) void attn_tc_kernel(
    const float* __restrict__ qkv, float* __restrict__ attn_out)
{
    __shared__ __align__(16) float Ks[2][64][20];
    __shared__ __align__(16) float Vs[2][64][24];
    __shared__ __align__(16) float Ps[4][16][68];

    const int h    = blockIdx.y;
    const int qt   = (int)gridDim.x - 1 - (int)blockIdx.x;  // heavy tiles first
    const int tid  = threadIdx.x;
    const int lane = tid & 31;
    const int w    = tid >> 5;
    const int g    = lane >> 2;
    const int t4   = lane & 3;
    const int qbase = qt * 64 + w * 16;

    // per-thread K/V chunk load coords (2 x float4 each)
    const int key0 = tid >> 2;           // 0..31
    const int kc4  = (tid & 3) * 4;      // 0,4,8,12

    auto prefetch = [&](int ci) {
        const int st = ci & 1;
        const float* kp = qkv + (size_t)(ci * 64 + key0) * (3 * C_EMB)
                          + C_EMB + h * HDIM + kc4;
        CP_ASYNC16((uint32_t)__cvta_generic_to_shared(&Ks[st][key0     ][kc4]), kp);
        CP_ASYNC16((uint32_t)__cvta_generic_to_shared(&Vs[st][key0     ][kc4]), kp + C_EMB);
        const float* kp2 = kp + (size_t)32 * (3 * C_EMB);
        CP_ASYNC16((uint32_t)__cvta_generic_to_shared(&Ks[st][key0 + 32][kc4]), kp2);
        CP_ASYNC16((uint32_t)__cvta_generic_to_shared(&Vs[st][key0 + 32][kc4]), kp2 + C_EMB);
    };

    // Q fragments (scaled by 0.25 — exact power of 2, stays tf32)
    uint32_t qa[2][4];
    {
        const float* qp = qkv + (size_t)qbase * (3 * C_EMB) + h * HDIM;
#pragma unroll
        for (int kt = 0; kt < 2; kt++) {
            qa[kt][0] = __float_as_uint(qp[(size_t)g       * (3 * C_EMB) + kt * 8 + t4    ] * 0.25f);
            qa[kt][1] = __float_as_uint(qp[(size_t)(g + 8) * (3 * C_EMB) + kt * 8 + t4    ] * 0.25f);
            qa[kt][2] = __float_as_uint(qp[(size_t)g       * (3 * C_EMB) + kt * 8 + t4 + 4] * 0.25f);
            qa[kt][3] = __float_as_uint(qp[(size_t)(g + 8) * (3 * C_EMB) + kt * 8 + t4 + 4] * 0.25f);
        }
    }

    float o[2][4];
#pragma unroll
    for (int nt = 0; nt < 2; nt++)
#pragma unroll
        for (int i = 0; i < 4; i++) o[nt][i] = 0.f;
    float m0 = -1e30f, m1 = -1e30f, l0 = 0.f, l1 = 0.f;

    const int nch = qt + 1;
    prefetch(0);
    CP_COMMIT();

    for (int ci = 0; ci < nch; ci++) {
        const int k0 = ci * 64;
        const int st = ci & 1;
        CP_WAIT(0);
        __syncthreads();          // chunk ci visible to all; prior readers done
        if (ci + 1 < nch) {
            prefetch(ci + 1);
            CP_COMMIT();
        }

        // scores S = Q @ K^T  (16 x 64 per warp)
        float sf[8][4];
#pragma unroll
        for (int ns = 0; ns < 8; ns++) {
            sf[ns][0] = 0.f; sf[ns][1] = 0.f; sf[ns][2] = 0.f; sf[ns][3] = 0.f;
#pragma unroll
            for (int kt = 0; kt < 2; kt++) {
                uint32_t b0 = __float_as_uint(Ks[st][ns * 8 + g][kt * 8 + t4    ]);
                uint32_t b1 = __float_as_uint(Ks[st][ns * 8 + g][kt * 8 + t4 + 4]);
                mma_tf32(sf[ns], qa[kt], b0, b1);
            }
        }

        // causal mask (diagonal chunk only)
        if (k0 + 63 > qbase) {
            const int r0 = qbase + g, r1 = r0 + 8;
#pragma unroll
            for (int ns = 0; ns < 8; ns++) {
                int col = k0 + ns * 8 + 2 * t4;
                if (col     > r0) sf[ns][0] = -1e30f;
                if (col + 1 > r0) sf[ns][1] = -1e30f;
                if (col     > r1) sf[ns][2] = -1e30f;
                if (col + 1 > r1) sf[ns][3] = -1e30f;
            }
        }

        // row max via shfl over t4 lanes
        float rm0 = -1e30f, rm1 = -1e30f;
#pragma unroll
        for (int ns = 0; ns < 8; ns++) {
            rm0 = fmaxf(rm0, fmaxf(sf[ns][0], sf[ns][1]));
            rm1 = fmaxf(rm1, fmaxf(sf[ns][2], sf[ns][3]));
        }
        rm0 = fmaxf(rm0, __shfl_xor_sync(0xffffffffu, rm0, 1));
        rm0 = fmaxf(rm0, __shfl_xor_sync(0xffffffffu, rm0, 2));
        rm1 = fmaxf(rm1, __shfl_xor_sync(0xffffffffu, rm1, 1));
        rm1 = fmaxf(rm1, __shfl_xor_sync(0xffffffffu, rm1, 2));

        float nm0 = fmaxf(m0, rm0), nm1 = fmaxf(m1, rm1);
        float corr0 = __expf(m0 - nm0), corr1 = __expf(m1 - nm1);
        m0 = nm0; m1 = nm1;
        l0 *= corr0; l1 *= corr1;
#pragma unroll
        for (int nt = 0; nt < 2; nt++) {
            o[nt][0] *= corr0; o[nt][1] *= corr0;
            o[nt][2] *= corr1; o[nt][3] *= corr1;
        }

        // p = exp(s - m); stage tf32 P into per-warp smem
#pragma unroll
        for (int ns = 0; ns < 8; ns++) {
            float p0 = __expf(sf[ns][0] - m0);
            float p1 = __expf(sf[ns][1] - m0);
            float p2 = __expf(sf[ns][2] - m1);
            float p3 = __expf(sf[ns][3] - m1);
            l0 += p0 + p1;
            l1 += p2 + p3;
            float2 v01, v23;
            v01.x = u2f(f2tf32(p0)); v01.y = u2f(f2tf32(p1));
            v23.x = u2f(f2tf32(p2)); v23.y = u2f(f2tf32(p3));
            *(float2*)&Ps[w][g    ][ns * 8 + 2 * t4] = v01;
            *(float2*)&Ps[w][g + 8][ns * 8 + 2 * t4] = v23;
        }
        __syncwarp();

        // O += P @ V
#pragma unroll
        for (int kt = 0; kt < 8; kt++) {
            uint32_t pa[4];
            pa[0] = __float_as_uint(Ps[w][g    ][kt * 8 + t4    ]);
            pa[1] = __float_as_uint(Ps[w][g + 8][kt * 8 + t4    ]);
            pa[2] = __float_as_uint(Ps[w][g    ][kt * 8 + t4 + 4]);
            pa[3] = __float_as_uint(Ps[w][g + 8][kt * 8 + t4 + 4]);
#pragma unroll
            for (int nt = 0; nt < 2; nt++) {
                uint32_t b0 = __float_as_uint(Vs[st][kt * 8 + t4    ][nt * 8 + g]);
                uint32_t b1 = __float_as_uint(Vs[st][kt * 8 + t4 + 4][nt * 8 + g]);
                mma_tf32(o[nt], pa, b0, b1);
            }
        }
        __syncwarp();   // Ps reads done before next chunk overwrites
    }

    l0 += __shfl_xor_sync(0xffffffffu, l0, 1);
    l0 += __shfl_xor_sync(0xffffffffu, l0, 2);
    l1 += __shfl_xor_sync(0xffffffffu, l1, 1);
    l1 += __shfl_xor_sync(0xffffffffu, l1, 2);
    const float inv0 = 1.f / l0, inv1 = 1.f / l1;

    // store tf32-rounded for the projection GEMM
    float* op = attn_out + (size_t)qbase * C_EMB + h * HDIM;
#pragma unroll
    for (int nt = 0; nt < 2; nt++) {
        float2 o0, o1;
        o0.x = u2f(f2tf32(o[nt][0] * inv0)); o0.y = u2f(f2tf32(o[nt][1] * inv0));
        o1.x = u2f(f2tf32(o[nt][2] * inv1)); o1.y = u2f(f2tf32(o[nt][3] * inv1));
        *(float2*)&op[(size_t)g       * C_EMB + nt * 8 + 2 * t4] = o0;
        *(float2*)&op[(size_t)(g + 8) * C_EMB + nt * 8 + 2 * t4] = o1;
    }
}

// ---------------------------------------------------------------------------
// Launch
// ---------------------------------------------------------------------------
extern "C" void kernel_launch(void* const* d_in, const int* in_sizes, int n_in,
                              void* d_out, int out_size)
{
    const float* x     = (const float*)d_in[0];
    // d_in[1] = attn_mask (ignored; is_causal wins in the reference)
    const float* W_qkv = (const float*)d_in[2];
    const float* b_qkv = (const float*)d_in[3];
    const float* W_out = (const float*)d_in[4];
    const float* b_out = (const float*)d_in[5];
    float* out = (float*)d_out;

    float *qkv_buf, *attn_buf, *x_t, *wq_t, *wo_t;
    cudaGetSymbolAddress((void**)&qkv_buf, g_qkv);
    cudaGetSymbolAddress((void**)&attn_buf, g_attn);
    cudaGetSymbolAddress((void**)&x_t, g_x);
    cudaGetSymbolAddress((void**)&wq_t, g_wqkv);
    cudaGetSymbolAddress((void**)&wo_t, g_wout);

    // 0) tf32-round the GEMM operands once
    {
        int n4;
        n4 = T_SEQ * C_EMB / 4;
        cvt_tf32_kernel<<<(n4 + 255) / 256, 256>>>(x, x_t, n4);
        n4 = C_EMB * 3 * C_EMB / 4;
        cvt_tf32_kernel<<<(n4 + 255) / 256, 256>>>(W_qkv, wq_t, n4);
        n4 = C_EMB * C_EMB / 4;
        cvt_tf32_kernel<<<(n4 + 255) / 256, 256>>>(W_out, wo_t, n4);
    }

    // 1) qkv = x @ W_qkv + b_qkv   (output tf32-rounded)
    {
        dim3 grid(3 * C_EMB / 128, T_SEQ / 128);
        gemm_tf32_bias_kernel<true><<<grid, 256>>>(x_t, wq_t, b_qkv, qkv_buf,
                                                   T_SEQ, 3 * C_EMB, C_EMB);
    }

    // 2) causal attention (output tf32-rounded)
    {
        dim3 grid(T_SEQ / 64, NHEADS);
        attn_tc_kernel<<<grid, 128>>>(qkv_buf, attn_buf);
    }

    // 3) out = attn @ W_out + b_out (full fp32 output)
    {
        dim3 grid(C_EMB / 128, T_SEQ / 128);
        gemm_tf32_bias_kernel<false><<<grid, 256>>>(attn_buf, wo_t, b_out, out,
                                                    T_SEQ, C_EMB, C_EMB);
    }
}

// round 5
// speedup vs baseline: 2.8116x; 1.0170x over previous
#include <cuda_runtime.h>
#include <cuda_bf16.h>
#include <cstdint>
#include <cstddef>

#define T_SEQ   2048
#define C_EMB   1024
#define HDIM    16
#define NHEADS  64

// Scratch (no cudaMalloc allowed)
__device__ float g_qkv[T_SEQ * 3 * C_EMB];
__device__ float g_attn[T_SEQ * C_EMB];
__device__ float g_x[T_SEQ * C_EMB];
__device__ float g_wqkv[C_EMB * 3 * C_EMB];
__device__ float g_wout[C_EMB * C_EMB];

__device__ __forceinline__ uint32_t f2tf32(float x) {
    uint32_t u;
    asm("cvt.rna.tf32.f32 %0, %1;" : "=r"(u) : "f"(x));
    return u;
}
__device__ __forceinline__ float u2f(uint32_t u) { return __uint_as_float(u); }

__device__ __forceinline__ void mma_tf32(float c[4], const uint32_t a[4],
                                         uint32_t b0, uint32_t b1) {
    asm volatile(
        "mma.sync.aligned.m16n8k8.row.col.f32.tf32.tf32.f32 "
        "{%0,%1,%2,%3}, {%4,%5,%6,%7}, {%8,%9}, {%0,%1,%2,%3};"
        : "+f"(c[0]), "+f"(c[1]), "+f"(c[2]), "+f"(c[3])
        : "r"(a[0]), "r"(a[1]), "r"(a[2]), "r"(a[3]), "r"(b0), "r"(b1));
}

#define CP_ASYNC16(dst, src) \
    asm volatile("cp.async.cg.shared.global [%0], [%1], 16;" :: "r"(dst), "l"(src))
#define CP_COMMIT() asm volatile("cp.async.commit_group;")
#define CP_WAIT(n)  asm volatile("cp.async.wait_group %0;" :: "n"(n))

// ---------------------------------------------------------------------------
// Elementwise tf32 rounding (prologue)
// ---------------------------------------------------------------------------
__global__ void cvt_tf32_kernel(const float* __restrict__ in,
                                float* __restrict__ out, int n4)
{
    int i = blockIdx.x * blockDim.x + threadIdx.x;
    if (i >= n4) return;
    float4 v = ((const float4*)in)[i];
    float4 o;
    o.x = u2f(f2tf32(v.x)); o.y = u2f(f2tf32(v.y));
    o.z = u2f(f2tf32(v.z)); o.w = u2f(f2tf32(v.w));
    ((float4*)out)[i] = o;
}

// ---------------------------------------------------------------------------
// TF32 GEMM, inputs pre-rounded to tf32. C = A @ B + bias, optional tf32
// rounding of C. 128x128 block, BK=16, 8 warps (4xM, 2xN), warp tile 32x64.
// 3-stage cp.async pipeline, one barrier per k-iter.
// ---------------------------------------------------------------------------
template <bool ROUND_OUT>
__global__ __launch_bounds__(256, 2) void gemm_tf32_bias_kernel(
    const float* __restrict__ A, const float* __restrict__ B,
    const float* __restrict__ bias, float* __restrict__ C,
    int M, int N, int K)
{
    __shared__ __align__(16) float As[3][128][20];
    __shared__ __align__(16) float Bs[3][16][136];

    const int tid  = threadIdx.x;
    const int lane = tid & 31;
    const int warp = tid >> 5;
    const int wm   = (warp & 3) * 32;
    const int wn   = (warp >> 2) * 64;
    const int g    = lane >> 2;
    const int t4   = lane & 3;
    const int row0 = blockIdx.y * 128;
    const int col0 = blockIdx.x * 128;

    float acc[2][8][4];
#pragma unroll
    for (int ms = 0; ms < 2; ms++)
#pragma unroll
        for (int ns = 0; ns < 8; ns++)
#pragma unroll
            for (int i = 0; i < 4; i++) acc[ms][ns][i] = 0.f;

    const int ar = tid >> 1;
    const int ak = (tid & 1) * 8;
    const int br = tid >> 5;
    const int bc = (tid & 31) * 4;

    auto issue_loads = [&](int k0, int st) {
        const float* ap = A + (size_t)(row0 + ar) * K + k0 + ak;
        CP_ASYNC16((uint32_t)__cvta_generic_to_shared(&As[st][ar][ak    ]), ap);
        CP_ASYNC16((uint32_t)__cvta_generic_to_shared(&As[st][ar][ak + 4]), ap + 4);
        const float* bp = B + (size_t)(k0 + br) * N + col0 + bc;
        CP_ASYNC16((uint32_t)__cvta_generic_to_shared(&Bs[st][br    ][bc]), bp);
        CP_ASYNC16((uint32_t)__cvta_generic_to_shared(&Bs[st][br + 8][bc]),
                   bp + (size_t)8 * N);
    };

    const int niter = K / 16;     // >= 2 always (K is 1024)
    issue_loads(0, 0);
    CP_COMMIT();
    issue_loads(16, 1);
    CP_COMMIT();

    for (int i = 0; i < niter; i++) {
        if (i + 2 < niter) { CP_WAIT(1); } else { CP_WAIT(0); }
        __syncthreads();
        if (i + 2 < niter) {
            issue_loads((i + 2) * 16, (i + 2) % 3);
            CP_COMMIT();
        }
        const int st = i % 3;
#pragma unroll
        for (int kk = 0; kk < 16; kk += 8) {
            uint32_t af[2][4];
#pragma unroll
            for (int ms = 0; ms < 2; ms++) {
                af[ms][0] = __float_as_uint(As[st][wm + ms * 16 + g    ][kk + t4    ]);
                af[ms][1] = __float_as_uint(As[st][wm + ms * 16 + g + 8][kk + t4    ]);
                af[ms][2] = __float_as_uint(As[st][wm + ms * 16 + g    ][kk + t4 + 4]);
                af[ms][3] = __float_as_uint(As[st][wm + ms * 16 + g + 8][kk + t4 + 4]);
            }
            uint32_t bf[8][2];
#pragma unroll
            for (int ns = 0; ns < 8; ns++) {
                bf[ns][0] = __float_as_uint(Bs[st][kk + t4    ][wn + ns * 8 + g]);
                bf[ns][1] = __float_as_uint(Bs[st][kk + t4 + 4][wn + ns * 8 + g]);
            }
#pragma unroll
            for (int ms = 0; ms < 2; ms++)
#pragma unroll
                for (int ns = 0; ns < 8; ns++)
                    mma_tf32(acc[ms][ns], af[ms], bf[ns][0], bf[ns][1]);
        }
    }
    // NOTE: compute of the last iter needs no trailing barrier.

#pragma unroll
    for (int ms = 0; ms < 2; ms++) {
#pragma unroll
        for (int ns = 0; ns < 8; ns++) {
            int r = row0 + wm + ms * 16 + g;
            int c = col0 + wn + ns * 8 + t4 * 2;
            float2 bv = *(const float2*)(bias + c);
            float2 o0, o1;
            o0.x = acc[ms][ns][0] + bv.x; o0.y = acc[ms][ns][1] + bv.y;
            o1.x = acc[ms][ns][2] + bv.x; o1.y = acc[ms][ns][3] + bv.y;
            if (ROUND_OUT) {
                o0.x = u2f(f2tf32(o0.x)); o0.y = u2f(f2tf32(o0.y));
                o1.x = u2f(f2tf32(o1.x)); o1.y = u2f(f2tf32(o1.y));
            }
            *(float2*)(C + (size_t)r * N + c) = o0;
            *(float2*)(C + (size_t)(r + 8) * N + c) = o1;
        }
    }
}

// ---------------------------------------------------------------------------
// Tensor-core flash attention (causal), 64 heads x dim 16.
// Block: 1 head x 64 q-rows, 4 warps (16 q-rows each). 64-key chunks,
// cp.async double-buffered. P@V computed as O^T = V^T @ P^T: the P^T
// B-fragments are built from score C-fragments with warp shuffles —
// no P smem round-trip. Vs stride 40 (8*t4+g mod 32 -> conflict-free).
// ---------------------------------------------------------------------------
__global__ __launch_bounds__(128) void attn_tc_kernel(
    const float* __restrict__ qkv, float* __restrict__ attn_out)
{
    __shared__ __align__(16) float Ks[2][64][20];
    __shared__ __align__(16) float Vs[2][64][40];

    const unsigned F = 0xffffffffu;
    const int h    = blockIdx.y;
    const int qt   = (int)gridDim.x - 1 - (int)blockIdx.x;  // heavy tiles first
    const int tid  = threadIdx.x;
    const int lane = tid & 31;
    const int w    = tid >> 5;
    const int g    = lane >> 2;
    const int t4   = lane & 3;
    const int qbase = qt * 64 + w * 16;

    const int key0 = tid >> 2;           // 0..31
    const int kc4  = (tid & 3) * 4;      // 0,4,8,12

    auto prefetch = [&](int ci) {
        const int st = ci & 1;
        const float* kp = qkv + (size_t)(ci * 64 + key0) * (3 * C_EMB)
                          + C_EMB + h * HDIM + kc4;
        CP_ASYNC16((uint32_t)__cvta_generic_to_shared(&Ks[st][key0     ][kc4]), kp);
        CP_ASYNC16((uint32_t)__cvta_generic_to_shared(&Vs[st][key0     ][kc4]), kp + C_EMB);
        const float* kp2 = kp + (size_t)32 * (3 * C_EMB);
        CP_ASYNC16((uint32_t)__cvta_generic_to_shared(&Ks[st][key0 + 32][kc4]), kp2);
        CP_ASYNC16((uint32_t)__cvta_generic_to_shared(&Vs[st][key0 + 32][kc4]), kp2 + C_EMB);
    };

    // Q fragments (x0.25 exact; qkv already tf32)
    uint32_t qa[2][4];
    {
        const float* qp = qkv + (size_t)qbase * (3 * C_EMB) + h * HDIM;
#pragma unroll
        for (int kt = 0; kt < 2; kt++) {
            qa[kt][0] = __float_as_uint(qp[(size_t)g       * (3 * C_EMB) + kt * 8 + t4    ] * 0.25f);
            qa[kt][1] = __float_as_uint(qp[(size_t)(g + 8) * (3 * C_EMB) + kt * 8 + t4    ] * 0.25f);
            qa[kt][2] = __float_as_uint(qp[(size_t)g       * (3 * C_EMB) + kt * 8 + t4 + 4] * 0.25f);
            qa[kt][3] = __float_as_uint(qp[(size_t)(g + 8) * (3 * C_EMB) + kt * 8 + t4 + 4] * 0.25f);
        }
    }

    // O^T accumulators: o[nt] c-frag = O^T[dims g/g+8][qrows nt*8+2t4(+1)]
    float o[2][4];
#pragma unroll
    for (int nt = 0; nt < 2; nt++)
#pragma unroll
        for (int i = 0; i < 4; i++) o[nt][i] = 0.f;
    float m0 = -1e30f, m1 = -1e30f, l0 = 0.f, l1 = 0.f;

    const int nch = qt + 1;
    prefetch(0);
    CP_COMMIT();

    for (int ci = 0; ci < nch; ci++) {
        const int k0 = ci * 64;
        const int st = ci & 1;
        CP_WAIT(0);
        __syncthreads();
        if (ci + 1 < nch) {
            prefetch(ci + 1);
            CP_COMMIT();
        }

        // scores S = Q @ K^T  (16 x 64 per warp)
        float sf[8][4];
#pragma unroll
        for (int ns = 0; ns < 8; ns++) {
            sf[ns][0] = 0.f; sf[ns][1] = 0.f; sf[ns][2] = 0.f; sf[ns][3] = 0.f;
#pragma unroll
            for (int kt = 0; kt < 2; kt++) {
                uint32_t b0 = __float_as_uint(Ks[st][ns * 8 + g][kt * 8 + t4    ]);
                uint32_t b1 = __float_as_uint(Ks[st][ns * 8 + g][kt * 8 + t4 + 4]);
                mma_tf32(sf[ns], qa[kt], b0, b1);
            }
        }

        // causal mask (diagonal chunk only)
        if (k0 + 63 > qbase) {
            const int r0 = qbase + g, r1 = r0 + 8;
#pragma unroll
            for (int ns = 0; ns < 8; ns++) {
                int col = k0 + ns * 8 + 2 * t4;
                if (col     > r0) sf[ns][0] = -1e30f;
                if (col + 1 > r0) sf[ns][1] = -1e30f;
                if (col     > r1) sf[ns][2] = -1e30f;
                if (col + 1 > r1) sf[ns][3] = -1e30f;
            }
        }

        // row max over t4 lanes
        float rm0 = -1e30f, rm1 = -1e30f;
#pragma unroll
        for (int ns = 0; ns < 8; ns++) {
            rm0 = fmaxf(rm0, fmaxf(sf[ns][0], sf[ns][1]));
            rm1 = fmaxf(rm1, fmaxf(sf[ns][2], sf[ns][3]));
        }
        rm0 = fmaxf(rm0, __shfl_xor_sync(F, rm0, 1));
        rm0 = fmaxf(rm0, __shfl_xor_sync(F, rm0, 2));
        rm1 = fmaxf(rm1, __shfl_xor_sync(F, rm1, 1));
        rm1 = fmaxf(rm1, __shfl_xor_sync(F, rm1, 2));

        float nm0 = fmaxf(m0, rm0), nm1 = fmaxf(m1, rm1);
        float corr0 = __expf(m0 - nm0), corr1 = __expf(m1 - nm1);
        m0 = nm0; m1 = nm1;
        l0 *= corr0; l1 *= corr1;

        // rescale O^T: fetch corr of the qrows this lane's o-frags hold
        {
            float ca = __shfl_sync(F, corr0, 8 * t4);       // qrow 2t4
            float cb = __shfl_sync(F, corr0, 8 * t4 + 4);   // qrow 2t4+1
            float cc = __shfl_sync(F, corr1, 8 * t4);       // qrow 8+2t4
            float cd = __shfl_sync(F, corr1, 8 * t4 + 4);   // qrow 8+2t4+1
            o[0][0] *= ca; o[0][1] *= cb; o[0][2] *= ca; o[0][3] *= cb;
            o[1][0] *= cc; o[1][1] *= cd; o[1][2] *= cc; o[1][3] *= cd;
        }

        // p = exp(s - m) in place; accumulate l
#pragma unroll
        for (int ns = 0; ns < 8; ns++) {
            sf[ns][0] = __expf(sf[ns][0] - m0);
            sf[ns][1] = __expf(sf[ns][1] - m0);
            sf[ns][2] = __expf(sf[ns][2] - m1);
            sf[ns][3] = __expf(sf[ns][3] - m1);
            l0 += sf[ns][0] + sf[ns][1];
            l1 += sf[ns][2] + sf[ns][3];
        }

        // O^T += V^T @ P^T  (P^T B-frags via shuffles from score C-frags)
        const int src1 = 4 * g + (t4 >> 1);
        const int src2 = src1 + 2;
        const bool odd = (t4 & 1);
#pragma unroll
        for (int kt = 0; kt < 8; kt++) {
            uint32_t va[4];
            va[0] = __float_as_uint(Vs[st][kt * 8 + t4    ][g    ]);
            va[1] = __float_as_uint(Vs[st][kt * 8 + t4    ][g + 8]);
            va[2] = __float_as_uint(Vs[st][kt * 8 + t4 + 4][g    ]);
            va[3] = __float_as_uint(Vs[st][kt * 8 + t4 + 4][g + 8]);

            float s0 = __shfl_sync(F, sf[kt][0], src1);
            float s1 = __shfl_sync(F, sf[kt][1], src1);
            float s2 = __shfl_sync(F, sf[kt][2], src1);
            float s3 = __shfl_sync(F, sf[kt][3], src1);
            float u0 = __shfl_sync(F, sf[kt][0], src2);
            float u1 = __shfl_sync(F, sf[kt][1], src2);
            float u2 = __shfl_sync(F, sf[kt][2], src2);
            float u3 = __shfl_sync(F, sf[kt][3], src2);

            uint32_t b00 = f2tf32(odd ? s1 : s0);   // nt=0, b0
            uint32_t b01 = f2tf32(odd ? u1 : u0);   // nt=0, b1
            uint32_t b10 = f2tf32(odd ? s3 : s2);   // nt=1, b0
            uint32_t b11 = f2tf32(odd ? u3 : u2);   // nt=1, b1

            mma_tf32(o[0], va, b00, b01);
            mma_tf32(o[1], va, b10, b11);
        }
    }

    // reduce l over t4 lanes, then fetch per-qrow values for this lane's frags
    l0 += __shfl_xor_sync(F, l0, 1);
    l0 += __shfl_xor_sync(F, l0, 2);
    l1 += __shfl_xor_sync(F, l1, 1);
    l1 += __shfl_xor_sync(F, l1, 2);
    float la = __shfl_sync(F, l0, 8 * t4);       // qrow 2t4
    float lb = __shfl_sync(F, l0, 8 * t4 + 4);   // qrow 2t4+1
    float lc = __shfl_sync(F, l1, 8 * t4);       // qrow 8+2t4
    float ld = __shfl_sync(F, l1, 8 * t4 + 4);   // qrow 8+2t4+1
    const float ia = 1.f / la, ib = 1.f / lb, ic = 1.f / lc, id = 1.f / ld;

    // store O (transposing back), tf32-rounded for the projection GEMM
#pragma unroll
    for (int nt = 0; nt < 2; nt++) {
        int q0 = qbase + nt * 8 + 2 * t4;
        float va0 = (nt == 0) ? ia : ic;
        float va1 = (nt == 0) ? ib : id;
        float* r0 = attn_out + (size_t)q0 * C_EMB + h * HDIM;
        float* r1 = r0 + C_EMB;
        r0[g    ] = u2f(f2tf32(o[nt][0] * va0));
        r1[g    ] = u2f(f2tf32(o[nt][1] * va1));
        r0[g + 8] = u2f(f2tf32(o[nt][2] * va0));
        r1[g + 8] = u2f(f2tf32(o[nt][3] * va1));
    }
}

// ---------------------------------------------------------------------------
// Launch
// ---------------------------------------------------------------------------
extern "C" void kernel_launch(void* const* d_in, const int* in_sizes, int n_in,
                              void* d_out, int out_size)
{
    const float* x     = (const float*)d_in[0];
    // d_in[1] = attn_mask (ignored; is_causal wins in the reference)
    const float* W_qkv = (const float*)d_in[2];
    const float* b_qkv = (const float*)d_in[3];
    const float* W_out = (const float*)d_in[4];
    const float* b_out = (const float*)d_in[5];
    float* out = (float*)d_out;

    float *qkv_buf, *attn_buf, *x_t, *wq_t, *wo_t;
    cudaGetSymbolAddress((void**)&qkv_buf, g_qkv);
    cudaGetSymbolAddress((void**)&attn_buf, g_attn);
    cudaGetSymbolAddress((void**)&x_t, g_x);
    cudaGetSymbolAddress((void**)&wq_t, g_wqkv);
    cudaGetSymbolAddress((void**)&wo_t, g_wout);

    // 0) tf32-round GEMM operands once
    {
        int n4;
        n4 = T_SEQ * C_EMB / 4;
        cvt_tf32_kernel<<<(n4 + 255) / 256, 256>>>(x, x_t, n4);
        n4 = C_EMB * 3 * C_EMB / 4;
        cvt_tf32_kernel<<<(n4 + 255) / 256, 256>>>(W_qkv, wq_t, n4);
        n4 = C_EMB * C_EMB / 4;
        cvt_tf32_kernel<<<(n4 + 255) / 256, 256>>>(W_out, wo_t, n4);
    }

    // 1) qkv = x @ W_qkv + b_qkv   (tf32-rounded output)
    {
        dim3 grid(3 * C_EMB / 128, T_SEQ / 128);
        gemm_tf32_bias_kernel<true><<<grid, 256>>>(x_t, wq_t, b_qkv, qkv_buf,
                                                   T_SEQ, 3 * C_EMB, C_EMB);
    }

    // 2) causal attention (tf32-rounded output)
    {
        dim3 grid(T_SEQ / 64, NHEADS);
        attn_tc_kernel<<<grid, 128>>>(qkv_buf, attn_buf);
    }

    // 3) out = attn @ W_out + b_out (full fp32 output)
    {
        dim3 grid(C_EMB / 128, T_SEQ / 128);
        gemm_tf32_bias_kernel<false><<<grid, 256>>>(attn_buf, wo_t, b_out, out,
                                                    T_SEQ, C_EMB, C_EMB);
    }
}

// round 7
// speedup vs baseline: 2.8210x; 1.0033x over previous
#include <cuda_runtime.h>
#include <cuda_bf16.h>
#include <cstdint>
#include <cstddef>

#define T_SEQ   2048
#define C_EMB   1024
#define HDIM    16
#define NHEADS  64

// Scratch (no cudaMalloc allowed)
__device__ float g_qkv[T_SEQ * 3 * C_EMB];
__device__ float g_attn[T_SEQ * C_EMB];
__device__ float g_x[T_SEQ * C_EMB];
__device__ float g_wqkv[C_EMB * 3 * C_EMB];
__device__ float g_wout[C_EMB * C_EMB];

__device__ __forceinline__ uint32_t f2tf32(float x) {
    uint32_t u;
    asm("cvt.rna.tf32.f32 %0, %1;" : "=r"(u) : "f"(x));
    return u;
}
__device__ __forceinline__ float u2f(uint32_t u) { return __uint_as_float(u); }

__device__ __forceinline__ void mma_tf32(float c[4], const uint32_t a[4],
                                         uint32_t b0, uint32_t b1) {
    asm volatile(
        "mma.sync.aligned.m16n8k8.row.col.f32.tf32.tf32.f32 "
        "{%0,%1,%2,%3}, {%4,%5,%6,%7}, {%8,%9}, {%0,%1,%2,%3};"
        : "+f"(c[0]), "+f"(c[1]), "+f"(c[2]), "+f"(c[3])
        : "r"(a[0]), "r"(a[1]), "r"(a[2]), "r"(a[3]), "r"(b0), "r"(b1));
}

#define CP_ASYNC16(dst, src) \
    asm volatile("cp.async.cg.shared.global [%0], [%1], 16;" :: "r"(dst), "l"(src))
#define CP_COMMIT() asm volatile("cp.async.commit_group;")
#define CP_WAIT(n)  asm volatile("cp.async.wait_group %0;" :: "n"(n))

// ---------------------------------------------------------------------------
// Elementwise tf32 rounding (prologue)
// ---------------------------------------------------------------------------
__global__ void cvt_tf32_kernel(const float* __restrict__ in,
                                float* __restrict__ out, int n4)
{
    int i = blockIdx.x * blockDim.x + threadIdx.x;
    if (i >= n4) return;
    float4 v = ((const float4*)in)[i];
    float4 o;
    o.x = u2f(f2tf32(v.x)); o.y = u2f(f2tf32(v.y));
    o.z = u2f(f2tf32(v.z)); o.w = u2f(f2tf32(v.w));
    ((float4*)out)[i] = o;
}

// ---------------------------------------------------------------------------
// TF32 GEMM, inputs pre-rounded to tf32. C = A @ B + bias, optional tf32
// rounding of C. 128x128 CTA tile, BK=16, 4 warps (2xM, 2xN), warp tile
// 64x64 -> 1 LDS per MMA. 3-stage cp.async pipeline, one barrier per iter.
// ---------------------------------------------------------------------------
template <bool ROUND_OUT>
__global__ __launch_bounds__(128, 2) void gemm_tf32_bias_kernel(
    const float* __restrict__ A, const float* __restrict__ B,
    const float* __restrict__ bias, float* __restrict__ C,
    int M, int N, int K)
{
    __shared__ __align__(16) float As[3][128][20];
    __shared__ __align__(16) float Bs[3][16][136];

    const int tid  = threadIdx.x;
    const int lane = tid & 31;
    const int warp = tid >> 5;          // 0..3
    const int wm   = (warp >> 1) * 64;
    const int wn   = (warp & 1) * 64;
    const int g    = lane >> 2;
    const int t4   = lane & 3;
    const int row0 = blockIdx.y * 128;
    const int col0 = blockIdx.x * 128;

    float acc[4][8][4];
#pragma unroll
    for (int ms = 0; ms < 4; ms++)
#pragma unroll
        for (int ns = 0; ns < 8; ns++)
#pragma unroll
            for (int i = 0; i < 4; i++) acc[ms][ns][i] = 0.f;

    auto issue_loads = [&](int k0, int st) {
#pragma unroll
        for (int it = 0; it < 4; it++) {
            int lin = tid + it * 128;           // 0..511
            int r   = lin >> 2;                 // 0..127
            int kc  = (lin & 3) * 4;
            CP_ASYNC16((uint32_t)__cvta_generic_to_shared(&As[st][r][kc]),
                       A + (size_t)(row0 + r) * K + k0 + kc);
        }
#pragma unroll
        for (int it = 0; it < 4; it++) {
            int lin = tid + it * 128;
            int r   = lin >> 5;                 // 0..15
            int c4  = (lin & 31) * 4;
            CP_ASYNC16((uint32_t)__cvta_generic_to_shared(&Bs[st][r][c4]),
                       B + (size_t)(k0 + r) * N + col0 + c4);
        }
    };

    const int niter = K / 16;     // >= 3 always here (K = 1024)
    issue_loads(0, 0);
    CP_COMMIT();
    issue_loads(16, 1);
    CP_COMMIT();

    for (int i = 0; i < niter; i++) {
        if (i + 2 < niter) { CP_WAIT(1); } else { CP_WAIT(0); }
        __syncthreads();
        if (i + 2 < niter) {
            issue_loads((i + 2) * 16, (i + 2) % 3);
            CP_COMMIT();
        }
        const int st = i % 3;
#pragma unroll
        for (int kk = 0; kk < 16; kk += 8) {
            uint32_t af[4][4];
#pragma unroll
            for (int ms = 0; ms < 4; ms++) {
                af[ms][0] = __float_as_uint(As[st][wm + ms * 16 + g    ][kk + t4    ]);
                af[ms][1] = __float_as_uint(As[st][wm + ms * 16 + g + 8][kk + t4    ]);
                af[ms][2] = __float_as_uint(As[st][wm + ms * 16 + g    ][kk + t4 + 4]);
                af[ms][3] = __float_as_uint(As[st][wm + ms * 16 + g + 8][kk + t4 + 4]);
            }
            uint32_t bf[8][2];
#pragma unroll
            for (int ns = 0; ns < 8; ns++) {
                bf[ns][0] = __float_as_uint(Bs[st][kk + t4    ][wn + ns * 8 + g]);
                bf[ns][1] = __float_as_uint(Bs[st][kk + t4 + 4][wn + ns * 8 + g]);
            }
#pragma unroll
            for (int ms = 0; ms < 4; ms++)
#pragma unroll
                for (int ns = 0; ns < 8; ns++)
                    mma_tf32(acc[ms][ns], af[ms], bf[ns][0], bf[ns][1]);
        }
    }

#pragma unroll
    for (int ms = 0; ms < 4; ms++) {
#pragma unroll
        for (int ns = 0; ns < 8; ns++) {
            int r = row0 + wm + ms * 16 + g;
            int c = col0 + wn + ns * 8 + t4 * 2;
            float2 bv = *(const float2*)(bias + c);
            float2 o0, o1;
            o0.x = acc[ms][ns][0] + bv.x; o0.y = acc[ms][ns][1] + bv.y;
            o1.x = acc[ms][ns][2] + bv.x; o1.y = acc[ms][ns][3] + bv.y;
            if (ROUND_OUT) {
                o0.x = u2f(f2tf32(o0.x)); o0.y = u2f(f2tf32(o0.y));
                o1.x = u2f(f2tf32(o1.x)); o1.y = u2f(f2tf32(o1.y));
            }
            *(float2*)(C + (size_t)r * N + c) = o0;
            *(float2*)(C + (size_t)(r + 8) * N + c) = o1;
        }
    }
}

// ---------------------------------------------------------------------------
// Tensor-core flash attention (causal), 64 heads x dim 16.
// Block: 1 head x 128 q-rows, 8 warps (16 q-rows each). 64-key chunks,
// cp.async double-buffered. Warps skip compute on chunks fully after their
// rows (k0 > qbase+15) but keep the block barriers. O^T = V^T @ P^T with
// shuffle-built P^T fragments (no P smem round-trip).
// ---------------------------------------------------------------------------
__global__ __launch_bounds__(256) void attn_tc_kernel(
    const float* __restrict__ qkv, float* __restrict__ attn_out)
{
    __shared__ __align__(16) float Ks[2][64][20];
    __shared__ __align__(16) float Vs[2][64][40];

    const unsigned F = 0xffffffffu;
    const int h    = blockIdx.y;
    const int qt   = (int)gridDim.x - 1 - (int)blockIdx.x;  // heavy tiles first
    const int tid  = threadIdx.x;
    const int lane = tid & 31;
    const int w    = tid >> 5;          // 0..7
    const int g    = lane >> 2;
    const int t4   = lane & 3;
    const int qbase = qt * 128 + w * 16;

    const int key0 = tid >> 2;          // 0..63
    const int kc4  = (tid & 3) * 4;     // 0,4,8,12

    auto prefetch = [&](int ci) {
        const int st = ci & 1;
        const float* kp = qkv + (size_t)(ci * 64 + key0) * (3 * C_EMB)
                          + C_EMB + h * HDIM + kc4;
        CP_ASYNC16((uint32_t)__cvta_generic_to_shared(&Ks[st][key0][kc4]), kp);
        CP_ASYNC16((uint32_t)__cvta_generic_to_shared(&Vs[st][key0][kc4]), kp + C_EMB);
    };

    // Q fragments (x0.25 exact; qkv already tf32)
    uint32_t qa[2][4];
    {
        const float* qp = qkv + (size_t)qbase * (3 * C_EMB) + h * HDIM;
#pragma unroll
        for (int kt = 0; kt < 2; kt++) {
            qa[kt][0] = __float_as_uint(qp[(size_t)g       * (3 * C_EMB) + kt * 8 + t4    ] * 0.25f);
            qa[kt][1] = __float_as_uint(qp[(size_t)(g + 8) * (3 * C_EMB) + kt * 8 + t4    ] * 0.25f);
            qa[kt][2] = __float_as_uint(qp[(size_t)g       * (3 * C_EMB) + kt * 8 + t4 + 4] * 0.25f);
            qa[kt][3] = __float_as_uint(qp[(size_t)(g + 8) * (3 * C_EMB) + kt * 8 + t4 + 4] * 0.25f);
        }
    }

    float o[2][4];
#pragma unroll
    for (int nt = 0; nt < 2; nt++)
#pragma unroll
        for (int i = 0; i < 4; i++) o[nt][i] = 0.f;
    float m0 = -1e30f, m1 = -1e30f, l0 = 0.f, l1 = 0.f;

    const int nch = qt * 2 + 2;     // chunks covering qt*128 + 128 keys
    prefetch(0);
    CP_COMMIT();

    for (int ci = 0; ci < nch; ci++) {
        const int k0 = ci * 64;
        const int st = ci & 1;
        CP_WAIT(0);
        __syncthreads();
        if (ci + 1 < nch) {
            prefetch(ci + 1);
            CP_COMMIT();
        }

        if (k0 <= qbase + 15) {     // chunk intersects this warp's causal range
            // scores S = Q @ K^T  (16 x 64 per warp)
            float sf[8][4];
#pragma unroll
            for (int ns = 0; ns < 8; ns++) {
                sf[ns][0] = 0.f; sf[ns][1] = 0.f; sf[ns][2] = 0.f; sf[ns][3] = 0.f;
#pragma unroll
                for (int kt = 0; kt < 2; kt++) {
                    uint32_t b0 = __float_as_uint(Ks[st][ns * 8 + g][kt * 8 + t4    ]);
                    uint32_t b1 = __float_as_uint(Ks[st][ns * 8 + g][kt * 8 + t4 + 4]);
                    mma_tf32(sf[ns], qa[kt], b0, b1);
                }
            }

            // causal mask (diagonal chunk only)
            if (k0 + 63 > qbase) {
                const int r0 = qbase + g, r1 = r0 + 8;
#pragma unroll
                for (int ns = 0; ns < 8; ns++) {
                    int col = k0 + ns * 8 + 2 * t4;
                    if (col     > r0) sf[ns][0] = -1e30f;
                    if (col + 1 > r0) sf[ns][1] = -1e30f;
                    if (col     > r1) sf[ns][2] = -1e30f;
                    if (col + 1 > r1) sf[ns][3] = -1e30f;
                }
            }

            // row max over t4 lanes
            float rm0 = -1e30f, rm1 = -1e30f;
#pragma unroll
            for (int ns = 0; ns < 8; ns++) {
                rm0 = fmaxf(rm0, fmaxf(sf[ns][0], sf[ns][1]));
                rm1 = fmaxf(rm1, fmaxf(sf[ns][2], sf[ns][3]));
            }
            rm0 = fmaxf(rm0, __shfl_xor_sync(F, rm0, 1));
            rm0 = fmaxf(rm0, __shfl_xor_sync(F, rm0, 2));
            rm1 = fmaxf(rm1, __shfl_xor_sync(F, rm1, 1));
            rm1 = fmaxf(rm1, __shfl_xor_sync(F, rm1, 2));

            float nm0 = fmaxf(m0, rm0), nm1 = fmaxf(m1, rm1);
            float corr0 = __expf(m0 - nm0), corr1 = __expf(m1 - nm1);
            m0 = nm0; m1 = nm1;
            l0 *= corr0; l1 *= corr1;

            {
                float ca = __shfl_sync(F, corr0, 8 * t4);
                float cb = __shfl_sync(F, corr0, 8 * t4 + 4);
                float cc = __shfl_sync(F, corr1, 8 * t4);
                float cd = __shfl_sync(F, corr1, 8 * t4 + 4);
                o[0][0] *= ca; o[0][1] *= cb; o[0][2] *= ca; o[0][3] *= cb;
                o[1][0] *= cc; o[1][1] *= cd; o[1][2] *= cc; o[1][3] *= cd;
            }

#pragma unroll
            for (int ns = 0; ns < 8; ns++) {
                sf[ns][0] = __expf(sf[ns][0] - m0);
                sf[ns][1] = __expf(sf[ns][1] - m0);
                sf[ns][2] = __expf(sf[ns][2] - m1);
                sf[ns][3] = __expf(sf[ns][3] - m1);
                l0 += sf[ns][0] + sf[ns][1];
                l1 += sf[ns][2] + sf[ns][3];
            }

            // O^T += V^T @ P^T (P^T B-frags via shuffles)
            const int src1 = 4 * g + (t4 >> 1);
            const int src2 = src1 + 2;
            const bool odd = (t4 & 1);
#pragma unroll
            for (int kt = 0; kt < 8; kt++) {
                uint32_t va[4];
                va[0] = __float_as_uint(Vs[st][kt * 8 + t4    ][g    ]);
                va[1] = __float_as_uint(Vs[st][kt * 8 + t4    ][g + 8]);
                va[2] = __float_as_uint(Vs[st][kt * 8 + t4 + 4][g    ]);
                va[3] = __float_as_uint(Vs[st][kt * 8 + t4 + 4][g + 8]);

                float s0 = __shfl_sync(F, sf[kt][0], src1);
                float s1 = __shfl_sync(F, sf[kt][1], src1);
                float s2 = __shfl_sync(F, sf[kt][2], src1);
                float s3 = __shfl_sync(F, sf[kt][3], src1);
                float u0 = __shfl_sync(F, sf[kt][0], src2);
                float u1 = __shfl_sync(F, sf[kt][1], src2);
                float u2 = __shfl_sync(F, sf[kt][2], src2);
                float u3 = __shfl_sync(F, sf[kt][3], src2);

                uint32_t b00 = f2tf32(odd ? s1 : s0);
                uint32_t b01 = f2tf32(odd ? u1 : u0);
                uint32_t b10 = f2tf32(odd ? s3 : s2);
                uint32_t b11 = f2tf32(odd ? u3 : u2);

                mma_tf32(o[0], va, b00, b01);
                mma_tf32(o[1], va, b10, b11);
            }
        }
    }

    l0 += __shfl_xor_sync(F, l0, 1);
    l0 += __shfl_xor_sync(F, l0, 2);
    l1 += __shfl_xor_sync(F, l1, 1);
    l1 += __shfl_xor_sync(F, l1, 2);
    float la = __shfl_sync(F, l0, 8 * t4);
    float lb = __shfl_sync(F, l0, 8 * t4 + 4);
    float lc = __shfl_sync(F, l1, 8 * t4);
    float ld = __shfl_sync(F, l1, 8 * t4 + 4);
    const float ia = 1.f / la, ib = 1.f / lb, ic = 1.f / lc, id = 1.f / ld;

#pragma unroll
    for (int nt = 0; nt < 2; nt++) {
        int q0 = qbase + nt * 8 + 2 * t4;
        float va0 = (nt == 0) ? ia : ic;
        float va1 = (nt == 0) ? ib : id;
        float* r0 = attn_out + (size_t)q0 * C_EMB + h * HDIM;
        float* r1 = r0 + C_EMB;
        r0[g    ] = u2f(f2tf32(o[nt][0] * va0));
        r1[g    ] = u2f(f2tf32(o[nt][1] * va1));
        r0[g + 8] = u2f(f2tf32(o[nt][2] * va0));
        r1[g + 8] = u2f(f2tf32(o[nt][3] * va1));
    }
}

// ---------------------------------------------------------------------------
// Launch
// ---------------------------------------------------------------------------
extern "C" void kernel_launch(void* const* d_in, const int* in_sizes, int n_in,
                              void* d_out, int out_size)
{
    const float* x     = (const float*)d_in[0];
    // d_in[1] = attn_mask (ignored; is_causal wins in the reference)
    const float* W_qkv = (const float*)d_in[2];
    const float* b_qkv = (const float*)d_in[3];
    const float* W_out = (const float*)d_in[4];
    const float* b_out = (const float*)d_in[5];
    float* out = (float*)d_out;

    float *qkv_buf, *attn_buf, *x_t, *wq_t, *wo_t;
    cudaGetSymbolAddress((void**)&qkv_buf, g_qkv);
    cudaGetSymbolAddress((void**)&attn_buf, g_attn);
    cudaGetSymbolAddress((void**)&x_t, g_x);
    cudaGetSymbolAddress((void**)&wq_t, g_wqkv);
    cudaGetSymbolAddress((void**)&wo_t, g_wout);

    // 0) tf32-round GEMM operands once
    {
        int n4;
        n4 = T_SEQ * C_EMB / 4;
        cvt_tf32_kernel<<<(n4 + 255) / 256, 256>>>(x, x_t, n4);
        n4 = C_EMB * 3 * C_EMB / 4;
        cvt_tf32_kernel<<<(n4 + 255) / 256, 256>>>(W_qkv, wq_t, n4);
        n4 = C_EMB * C_EMB / 4;
        cvt_tf32_kernel<<<(n4 + 255) / 256, 256>>>(W_out, wo_t, n4);
    }

    // 1) qkv = x @ W_qkv + b_qkv   (tf32-rounded output)
    {
        dim3 grid(3 * C_EMB / 128, T_SEQ / 128);
        gemm_tf32_bias_kernel<true><<<grid, 128>>>(x_t, wq_t, b_qkv, qkv_buf,
                                                   T_SEQ, 3 * C_EMB, C_EMB);
    }

    // 2) causal attention (tf32-rounded output)
    {
        dim3 grid(T_SEQ / 128, NHEADS);
        attn_tc_kernel<<<grid, 256>>>(qkv_buf, attn_buf);
    }

    // 3) out = attn @ W_out + b_out (full fp32 output)
    {
        dim3 grid(C_EMB / 128, T_SEQ / 128);
        gemm_tf32_bias_kernel<false><<<grid, 128>>>(attn_buf, wo_t, b_out, out,
                                                    T_SEQ, C_EMB, C_EMB);
    }
}

// round 9
// speedup vs baseline: 2.8784x; 1.0204x over previous
#include <cuda_runtime.h>
#include <cuda_bf16.h>
#include <cstdint>
#include <cstddef>

#define T_SEQ   2048
#define C_EMB   1024
#define HDIM    16
#define NHEADS  64

// Scratch (no cudaMalloc allowed)
__device__ float g_qkv[T_SEQ * 3 * C_EMB];
__device__ float g_attn[T_SEQ * C_EMB];
__device__ float g_x[T_SEQ * C_EMB];
__device__ float g_wqkv[C_EMB * 3 * C_EMB];
__device__ float g_wout[C_EMB * C_EMB];
__device__ __nv_bfloat16 g_vth[NHEADS * HDIM * T_SEQ];  // V^T hi bf16 [h][d][t]
__device__ __nv_bfloat16 g_vtl[NHEADS * HDIM * T_SEQ];  // V^T lo bf16 [h][d][t]

__device__ __forceinline__ uint32_t f2tf32(float x) {
    uint32_t u;
    asm("cvt.rna.tf32.f32 %0, %1;" : "=r"(u) : "f"(x));
    return u;
}
__device__ __forceinline__ float u2f(uint32_t u) { return __uint_as_float(u); }

__device__ __forceinline__ uint32_t pack_bf16x2(float lo, float hi) {
    uint32_t d;
    asm("cvt.rn.bf16x2.f32 %0, %1, %2;" : "=r"(d) : "f"(hi), "f"(lo));
    return d;
}

__device__ __forceinline__ void mma_tf32(float c[4], const uint32_t a[4],
                                         uint32_t b0, uint32_t b1) {
    asm volatile(
        "mma.sync.aligned.m16n8k8.row.col.f32.tf32.tf32.f32 "
        "{%0,%1,%2,%3}, {%4,%5,%6,%7}, {%8,%9}, {%0,%1,%2,%3};"
        : "+f"(c[0]), "+f"(c[1]), "+f"(c[2]), "+f"(c[3])
        : "r"(a[0]), "r"(a[1]), "r"(a[2]), "r"(a[3]), "r"(b0), "r"(b1));
}

__device__ __forceinline__ void mma_bf16(float c[4], const uint32_t a[4],
                                         uint32_t b0, uint32_t b1) {
    asm volatile(
        "mma.sync.aligned.m16n8k16.row.col.f32.bf16.bf16.f32 "
        "{%0,%1,%2,%3}, {%4,%5,%6,%7}, {%8,%9}, {%0,%1,%2,%3};"
        : "+f"(c[0]), "+f"(c[1]), "+f"(c[2]), "+f"(c[3])
        : "r"(a[0]), "r"(a[1]), "r"(a[2]), "r"(a[3]), "r"(b0), "r"(b1));
}

#define CP_ASYNC16(dst, src) \
    asm volatile("cp.async.cg.shared.global [%0], [%1], 16;" :: "r"(dst), "l"(src))
#define CP_COMMIT() asm volatile("cp.async.commit_group;")
#define CP_WAIT(n)  asm volatile("cp.async.wait_group %0;" :: "n"(n))

// ---------------------------------------------------------------------------
// Prologue: elementwise tf32 rounding
// ---------------------------------------------------------------------------
__global__ void cvt_tf32_kernel(const float* __restrict__ in,
                                float* __restrict__ out, int n4)
{
    int i = blockIdx.x * blockDim.x + threadIdx.x;
    if (i >= n4) return;
    float4 v = ((const float4*)in)[i];
    float4 o;
    o.x = u2f(f2tf32(v.x)); o.y = u2f(f2tf32(v.y));
    o.z = u2f(f2tf32(v.z)); o.w = u2f(f2tf32(v.w));
    ((float4*)out)[i] = o;
}

// ---------------------------------------------------------------------------
// V transpose to hi/lo bf16: v = hi + lo (split exact to ~4e-6 relative)
// g_vth/g_vtl [h][d][t].  grid (64 heads, 16 token-tiles), 128 threads.
// ---------------------------------------------------------------------------
__global__ void vt_kernel(const float* __restrict__ qkv,
                          __nv_bfloat16* __restrict__ vth,
                          __nv_bfloat16* __restrict__ vtl)
{
    __shared__ __nv_bfloat16 smh[16][132];
    __shared__ __nv_bfloat16 sml[16][132];
    const int h   = blockIdx.x;
    const int tt  = blockIdx.y;
    const int tid = threadIdx.x;
    const int token = tt * 128 + tid;

    const float* vp = qkv + (size_t)token * (3 * C_EMB) + 2 * C_EMB + h * HDIM;
#pragma unroll
    for (int c = 0; c < 16; c++) {
        float v = vp[c];
        __nv_bfloat16 hb = __float2bfloat16(v);
        float lo = v - __bfloat162float(hb);
        smh[c][tid] = hb;
        sml[c][tid] = __float2bfloat16(lo);
    }
    __syncthreads();

    const int d  = tid >> 3;           // 0..15
    const int c0 = (tid & 7) * 16;     // 0..112
    size_t base = ((size_t)(h * HDIM + d)) * T_SEQ + tt * 128 + c0;
    uint32_t* oh = (uint32_t*)(vth + base);
    uint32_t* ol = (uint32_t*)(vtl + base);
#pragma unroll
    for (int i = 0; i < 8; i++) {
        oh[i] = *(const uint32_t*)&smh[d][c0 + 2 * i];
        ol[i] = *(const uint32_t*)&sml[d][c0 + 2 * i];
    }
}

// ---------------------------------------------------------------------------
// TF32 GEMM (unchanged): C = A @ B + bias, 128x128 CTA, BK=16,
// 4 warps, warp tile 64x64, 3-stage cp.async.
// ---------------------------------------------------------------------------
template <bool ROUND_OUT>
__global__ __launch_bounds__(128, 2) void gemm_tf32_bias_kernel(
    const float* __restrict__ A, const float* __restrict__ B,
    const float* __restrict__ bias, float* __restrict__ C,
    int M, int N, int K)
{
    __shared__ __align__(16) float As[3][128][20];
    __shared__ __align__(16) float Bs[3][16][136];

    const int tid  = threadIdx.x;
    const int lane = tid & 31;
    const int warp = tid >> 5;
    const int wm   = (warp >> 1) * 64;
    const int wn   = (warp & 1) * 64;
    const int g    = lane >> 2;
    const int t4   = lane & 3;
    const int row0 = blockIdx.y * 128;
    const int col0 = blockIdx.x * 128;

    float acc[4][8][4];
#pragma unroll
    for (int ms = 0; ms < 4; ms++)
#pragma unroll
        for (int ns = 0; ns < 8; ns++)
#pragma unroll
            for (int i = 0; i < 4; i++) acc[ms][ns][i] = 0.f;

    auto issue_loads = [&](int k0, int st) {
#pragma unroll
        for (int it = 0; it < 4; it++) {
            int lin = tid + it * 128;
            int r   = lin >> 2;
            int kc  = (lin & 3) * 4;
            CP_ASYNC16((uint32_t)__cvta_generic_to_shared(&As[st][r][kc]),
                       A + (size_t)(row0 + r) * K + k0 + kc);
        }
#pragma unroll
        for (int it = 0; it < 4; it++) {
            int lin = tid + it * 128;
            int r   = lin >> 5;
            int c4  = (lin & 31) * 4;
            CP_ASYNC16((uint32_t)__cvta_generic_to_shared(&Bs[st][r][c4]),
                       B + (size_t)(k0 + r) * N + col0 + c4);
        }
    };

    const int niter = K / 16;
    issue_loads(0, 0);
    CP_COMMIT();
    issue_loads(16, 1);
    CP_COMMIT();

    for (int i = 0; i < niter; i++) {
        if (i + 2 < niter) { CP_WAIT(1); } else { CP_WAIT(0); }
        __syncthreads();
        if (i + 2 < niter) {
            issue_loads((i + 2) * 16, (i + 2) % 3);
            CP_COMMIT();
        }
        const int st = i % 3;
#pragma unroll
        for (int kk = 0; kk < 16; kk += 8) {
            uint32_t af[4][4];
#pragma unroll
            for (int ms = 0; ms < 4; ms++) {
                af[ms][0] = __float_as_uint(As[st][wm + ms * 16 + g    ][kk + t4    ]);
                af[ms][1] = __float_as_uint(As[st][wm + ms * 16 + g + 8][kk + t4    ]);
                af[ms][2] = __float_as_uint(As[st][wm + ms * 16 + g    ][kk + t4 + 4]);
                af[ms][3] = __float_as_uint(As[st][wm + ms * 16 + g + 8][kk + t4 + 4]);
            }
            uint32_t bf[8][2];
#pragma unroll
            for (int ns = 0; ns < 8; ns++) {
                bf[ns][0] = __float_as_uint(Bs[st][kk + t4    ][wn + ns * 8 + g]);
                bf[ns][1] = __float_as_uint(Bs[st][kk + t4 + 4][wn + ns * 8 + g]);
            }
#pragma unroll
            for (int ms = 0; ms < 4; ms++)
#pragma unroll
                for (int ns = 0; ns < 8; ns++)
                    mma_tf32(acc[ms][ns], af[ms], bf[ns][0], bf[ns][1]);
        }
    }

#pragma unroll
    for (int ms = 0; ms < 4; ms++) {
#pragma unroll
        for (int ns = 0; ns < 8; ns++) {
            int r = row0 + wm + ms * 16 + g;
            int c = col0 + wn + ns * 8 + t4 * 2;
            float2 bv = *(const float2*)(bias + c);
            float2 o0, o1;
            o0.x = acc[ms][ns][0] + bv.x; o0.y = acc[ms][ns][1] + bv.y;
            o1.x = acc[ms][ns][2] + bv.x; o1.y = acc[ms][ns][3] + bv.y;
            if (ROUND_OUT) {
                o0.x = u2f(f2tf32(o0.x)); o0.y = u2f(f2tf32(o0.y));
                o1.x = u2f(f2tf32(o1.x)); o1.y = u2f(f2tf32(o1.y));
            }
            *(float2*)(C + (size_t)r * N + c) = o0;
            *(float2*)(C + (size_t)(r + 8) * N + c) = o1;
        }
    }
}

// ---------------------------------------------------------------------------
// Flash attention (causal): scores tf32 mma; P@V via bf16 m16n8k16 with
// hi/lo splitting of BOTH P and V (3 mma terms, lo*lo dropped ~4e-6).
// Score C-fragments pack directly into bf16 A-fragments: zero shuffles.
// Block: 1 head x 64 q-rows, 4 warps. 64-key chunks double-buffered.
// ---------------------------------------------------------------------------
__global__ __launch_bounds__(128) void attn_tc_kernel(
    const float* __restrict__ qkv,
    const __nv_bfloat16* __restrict__ vth,
    const __nv_bfloat16* __restrict__ vtl,
    float* __restrict__ attn_out)
{
    __shared__ __align__(16) float Ks[2][64][20];
    __shared__ __align__(16) __nv_bfloat16 Vh[2][16][72];
    __shared__ __align__(16) __nv_bfloat16 Vl[2][16][72];

    const unsigned F = 0xffffffffu;
    const int h    = blockIdx.y;
    const int qt   = (int)gridDim.x - 1 - (int)blockIdx.x;  // heavy tiles first
    const int tid  = threadIdx.x;
    const int lane = tid & 31;
    const int w    = tid >> 5;
    const int g    = lane >> 2;
    const int t4   = lane & 3;
    const int qbase = qt * 64 + w * 16;

    // K load coords: 64 rows x 16 floats; 2 granules per thread
    const int krow = tid >> 1;
    const int kcol = (tid & 1) * 8;
    // Vt load coords: 16 dims x 64 bf16 = 128B/dim; 1 granule per thread/array
    const int vdim = tid >> 3;
    const int vseg = (tid & 7) * 8;

    auto prefetch = [&](int ci) {
        const int st = ci & 1;
        const float* kp = qkv + (size_t)(ci * 64 + krow) * (3 * C_EMB)
                          + C_EMB + h * HDIM + kcol;
        CP_ASYNC16((uint32_t)__cvta_generic_to_shared(&Ks[st][krow][kcol    ]), kp);
        CP_ASYNC16((uint32_t)__cvta_generic_to_shared(&Ks[st][krow][kcol + 4]), kp + 4);
        size_t vbase = (size_t)(h * HDIM + vdim) * T_SEQ + ci * 64 + vseg;
        CP_ASYNC16((uint32_t)__cvta_generic_to_shared(&Vh[st][vdim][vseg]), vth + vbase);
        CP_ASYNC16((uint32_t)__cvta_generic_to_shared(&Vl[st][vdim][vseg]), vtl + vbase);
    };

    // Q fragments (x0.25 exact; qkv already tf32-rounded)
    uint32_t qa[2][4];
    {
        const float* qp = qkv + (size_t)qbase * (3 * C_EMB) + h * HDIM;
#pragma unroll
        for (int kt = 0; kt < 2; kt++) {
            qa[kt][0] = __float_as_uint(qp[(size_t)g       * (3 * C_EMB) + kt * 8 + t4    ] * 0.25f);
            qa[kt][1] = __float_as_uint(qp[(size_t)(g + 8) * (3 * C_EMB) + kt * 8 + t4    ] * 0.25f);
            qa[kt][2] = __float_as_uint(qp[(size_t)g       * (3 * C_EMB) + kt * 8 + t4 + 4] * 0.25f);
            qa[kt][3] = __float_as_uint(qp[(size_t)(g + 8) * (3 * C_EMB) + kt * 8 + t4 + 4] * 0.25f);
        }
    }

    // O accumulators, natural layout: o[nt][0,1] -> row g, o[nt][2,3] -> row g+8
    float o[2][4];
#pragma unroll
    for (int nt = 0; nt < 2; nt++)
#pragma unroll
        for (int i = 0; i < 4; i++) o[nt][i] = 0.f;
    float m0 = -1e30f, m1 = -1e30f, l0 = 0.f, l1 = 0.f;

    const int nch = qt + 1;
    prefetch(0);
    CP_COMMIT();

    for (int ci = 0; ci < nch; ci++) {
        const int k0 = ci * 64;
        const int st = ci & 1;
        CP_WAIT(0);
        __syncthreads();
        if (ci + 1 < nch) {
            prefetch(ci + 1);
            CP_COMMIT();
        }

        // scores S = Q @ K^T (16 x 64 per warp), tf32
        float sf[8][4];
#pragma unroll
        for (int ns = 0; ns < 8; ns++) {
            sf[ns][0] = 0.f; sf[ns][1] = 0.f; sf[ns][2] = 0.f; sf[ns][3] = 0.f;
#pragma unroll
            for (int kt = 0; kt < 2; kt++) {
                uint32_t b0 = __float_as_uint(Ks[st][ns * 8 + g][kt * 8 + t4    ]);
                uint32_t b1 = __float_as_uint(Ks[st][ns * 8 + g][kt * 8 + t4 + 4]);
                mma_tf32(sf[ns], qa[kt], b0, b1);
            }
        }

        // causal mask: only the diagonal chunk (ci == qt)
        if (ci == qt) {
            const int r0 = qbase + g, r1 = r0 + 8;
#pragma unroll
            for (int ns = 0; ns < 8; ns++) {
                int col = k0 + ns * 8 + 2 * t4;
                if (col     > r0) sf[ns][0] = -1e30f;
                if (col + 1 > r0) sf[ns][1] = -1e30f;
                if (col     > r1) sf[ns][2] = -1e30f;
                if (col + 1 > r1) sf[ns][3] = -1e30f;
            }
        }

        // row max over t4 lanes
        float rm0 = -1e30f, rm1 = -1e30f;
#pragma unroll
        for (int ns = 0; ns < 8; ns++) {
            rm0 = fmaxf(rm0, fmaxf(sf[ns][0], sf[ns][1]));
            rm1 = fmaxf(rm1, fmaxf(sf[ns][2], sf[ns][3]));
        }
        rm0 = fmaxf(rm0, __shfl_xor_sync(F, rm0, 1));
        rm0 = fmaxf(rm0, __shfl_xor_sync(F, rm0, 2));
        rm1 = fmaxf(rm1, __shfl_xor_sync(F, rm1, 1));
        rm1 = fmaxf(rm1, __shfl_xor_sync(F, rm1, 2));

        float nm0 = fmaxf(m0, rm0), nm1 = fmaxf(m1, rm1);
        float corr0 = __expf(m0 - nm0), corr1 = __expf(m1 - nm1);
        m0 = nm0; m1 = nm1;
        l0 *= corr0; l1 *= corr1;
#pragma unroll
        for (int nt = 0; nt < 2; nt++) {
            o[nt][0] *= corr0; o[nt][1] *= corr0;
            o[nt][2] *= corr1; o[nt][3] *= corr1;
        }

        // p = exp(s - m); accumulate l
#pragma unroll
        for (int ns = 0; ns < 8; ns++) {
            sf[ns][0] = __expf(sf[ns][0] - m0);
            sf[ns][1] = __expf(sf[ns][1] - m0);
            sf[ns][2] = __expf(sf[ns][2] - m1);
            sf[ns][3] = __expf(sf[ns][3] - m1);
            l0 += sf[ns][0] + sf[ns][1];
            l1 += sf[ns][2] + sf[ns][3];
        }

        // O += P @ V with hi/lo bf16 splitting (3 terms; lo*lo dropped)
#pragma unroll
        for (int kt = 0; kt < 4; kt++) {
            uint32_t ph[4], pl[4];
#pragma unroll
            for (int r = 0; r < 4; r++) {
                const float a = sf[2 * kt + (r >> 1)][(r & 1) * 2    ];
                const float b = sf[2 * kt + (r >> 1)][(r & 1) * 2 + 1];
                uint32_t hp = pack_bf16x2(a, b);
                ph[r] = hp;
                float ha = u2f(hp << 16);
                float hb = u2f(hp & 0xffff0000u);
                pl[r] = pack_bf16x2(a - ha, b - hb);
            }
            // reorder: pa index mapping {0,1,2,3} -> rows (g,k0..7),(g+8,k0..7),
            // (g,k8..15),(g+8,k8..15) => ph built as [r>>1 selects kt-half][r&1 row]
            uint32_t pah[4] = { ph[0], ph[1], ph[2], ph[3] };
            uint32_t pal[4] = { pl[0], pl[1], pl[2], pl[3] };
#pragma unroll
            for (int nt = 0; nt < 2; nt++) {
                uint32_t bh0 = *(const uint32_t*)&Vh[st][nt * 8 + g][kt * 16 + 2 * t4    ];
                uint32_t bh1 = *(const uint32_t*)&Vh[st][nt * 8 + g][kt * 16 + 8 + 2 * t4];
                uint32_t bl0 = *(const uint32_t*)&Vl[st][nt * 8 + g][kt * 16 + 2 * t4    ];
                uint32_t bl1 = *(const uint32_t*)&Vl[st][nt * 8 + g][kt * 16 + 8 + 2 * t4];
                mma_bf16(o[nt], pah, bh0, bh1);
                mma_bf16(o[nt], pah, bl0, bl1);
                mma_bf16(o[nt], pal, bh0, bh1);
            }
        }
    }

    // reduce l over t4 lanes; rows g / g+8 use l0 / l1 directly
    l0 += __shfl_xor_sync(F, l0, 1);
    l0 += __shfl_xor_sync(F, l0, 2);
    l1 += __shfl_xor_sync(F, l1, 1);
    l1 += __shfl_xor_sync(F, l1, 2);
    const float inv0 = 1.f / l0, inv1 = 1.f / l1;

    // store O (natural layout), tf32-rounded for the projection GEMM
    float* r0 = attn_out + (size_t)(qbase + g    ) * C_EMB + h * HDIM;
    float* r1 = attn_out + (size_t)(qbase + g + 8) * C_EMB + h * HDIM;
#pragma unroll
    for (int nt = 0; nt < 2; nt++) {
        float2 v0, v1;
        v0.x = u2f(f2tf32(o[nt][0] * inv0)); v0.y = u2f(f2tf32(o[nt][1] * inv0));
        v1.x = u2f(f2tf32(o[nt][2] * inv1)); v1.y = u2f(f2tf32(o[nt][3] * inv1));
        *(float2*)(r0 + nt * 8 + 2 * t4) = v0;
        *(float2*)(r1 + nt * 8 + 2 * t4) = v1;
    }
}

// ---------------------------------------------------------------------------
// Launch
// ---------------------------------------------------------------------------
extern "C" void kernel_launch(void* const* d_in, const int* in_sizes, int n_in,
                              void* d_out, int out_size)
{
    const float* x     = (const float*)d_in[0];
    // d_in[1] = attn_mask (ignored; is_causal wins in the reference)
    const float* W_qkv = (const float*)d_in[2];
    const float* b_qkv = (const float*)d_in[3];
    const float* W_out = (const float*)d_in[4];
    const float* b_out = (const float*)d_in[5];
    float* out = (float*)d_out;

    float *qkv_buf, *attn_buf, *x_t, *wq_t, *wo_t;
    __nv_bfloat16 *vth_buf, *vtl_buf;
    cudaGetSymbolAddress((void**)&qkv_buf, g_qkv);
    cudaGetSymbolAddress((void**)&attn_buf, g_attn);
    cudaGetSymbolAddress((void**)&x_t, g_x);
    cudaGetSymbolAddress((void**)&wq_t, g_wqkv);
    cudaGetSymbolAddress((void**)&wo_t, g_wout);
    cudaGetSymbolAddress((void**)&vth_buf, g_vth);
    cudaGetSymbolAddress((void**)&vtl_buf, g_vtl);

    // 0) tf32-round GEMM operands once
    {
        int n4;
        n4 = T_SEQ * C_EMB / 4;
        cvt_tf32_kernel<<<(n4 + 255) / 256, 256>>>(x, x_t, n4);
        n4 = C_EMB * 3 * C_EMB / 4;
        cvt_tf32_kernel<<<(n4 + 255) / 256, 256>>>(W_qkv, wq_t, n4);
        n4 = C_EMB * C_EMB / 4;
        cvt_tf32_kernel<<<(n4 + 255) / 256, 256>>>(W_out, wo_t, n4);
    }

    // 1) qkv = x @ W_qkv + b_qkv   (tf32-rounded output)
    {
        dim3 grid(3 * C_EMB / 128, T_SEQ / 128);
        gemm_tf32_bias_kernel<true><<<grid, 128>>>(x_t, wq_t, b_qkv, qkv_buf,
                                                   T_SEQ, 3 * C_EMB, C_EMB);
    }

    // 1b) V -> hi/lo bf16 transposed [h][d][t]
    {
        dim3 grid(NHEADS, T_SEQ / 128);
        vt_kernel<<<grid, 128>>>(qkv_buf, vth_buf, vtl_buf);
    }

    // 2) causal attention (tf32-rounded output)
    {
        dim3 grid(T_SEQ / 64, NHEADS);
        attn_tc_kernel<<<grid, 128>>>(qkv_buf, vth_buf, vtl_buf, attn_buf);
    }

    // 3) out = attn @ W_out + b_out (full fp32 output)
    {
        dim3 grid(C_EMB / 128, T_SEQ / 128);
        gemm_tf32_bias_kernel<false><<<grid, 128>>>(attn_buf, wo_t, b_out, out,
                                                    T_SEQ, C_EMB, C_EMB);
    }
}